// round 14
// baseline (speedup 1.0000x reference)
#include <cuda_runtime.h>

#define NN 32768
#define CC 64
#define KK 16
#define SS 8
#define EE (NN * KK)
#define EPS 1e-5f

// ---------------- scratch ----------------
__device__ float g_y1[NN * CC];
__device__ float g_k[NN * CC];
__device__ float g_q[NN * CC];
__device__ float g_v[NN * CC];
__device__ float g_a1[EE * SS];
__device__ float g_out[NN * CC];
__device__ float g_y3[NN * CC];
__device__ int   g_src[EE];
__device__ float4 g_t4[EE];
__device__ float g_WT[5][4096];   // [j*64+o]; 0=W1,1=Wk,2=Wq,3=Wv,4=W3

#define ST_BN1 0
#define ST_T   128
#define ST_W1  134
#define ST_W2  262
#define ST_BN2 278
#define ST_BN3 406
#define ST_TOT 534
__device__ double g_st[ST_TOT];

#define INV_N  (1.0 / (double)NN)
#define INV_E  (1.0 / (double)EE)

// dynamic smem: weights (4096) + X tile (128*68)
#define GEMM_SMEM ((4096 + 128 * 68) * 4)
// a0v kernel: smaller v tile (64 nodes)
#define A0V_SMEM  ((4096 + 64 * 68) * 4)
#define VBLK 512

__device__ __forceinline__ void bn_coef(int off, int nch, int c, double inv_cnt,
                                        const float* __restrict__ g,
                                        const float* __restrict__ b,
                                        float& scale, float& shift) {
    double m = g_st[off + c] * inv_cnt;
    double v = g_st[off + nch + c] * inv_cnt - m * m;
    float rs = rsqrtf(fmaxf((float)v, 0.f) + EPS);
    scale = rs * __ldg(&g[c]);
    shift = __ldg(&b[c]) - (float)m * scale;
}

// shared GEMM body: 128-node tile, 8 nodes x 4 outputs per thread
__device__ __forceinline__ void gemm_tile(const float* sWT, const float* sX,
                                          float* dstBase, int base, int tid,
                                          float bo0, float bo1, float bo2, float bo3) {
    int o0 = (tid & 15) * 4;
    int n0 = (tid >> 4) * 8;
    float acc[8][4];
    #pragma unroll
    for (int i = 0; i < 8; i++)
        #pragma unroll
        for (int c = 0; c < 4; c++) acc[i][c] = 0.f;
    #pragma unroll
    for (int j = 0; j < 64; j += 4) {
        float4 xv[8];
        #pragma unroll
        for (int i = 0; i < 8; i++) xv[i] = *(float4*)(sX + (n0 + i) * 68 + j);
        #pragma unroll
        for (int jj = 0; jj < 4; jj++) {
            float4 wv = *(float4*)(sWT + (j + jj) * 64 + o0);
            #pragma unroll
            for (int i = 0; i < 8; i++) {
                float h = ((const float*)&xv[i])[jj];
                acc[i][0] = fmaf(h, wv.x, acc[i][0]);
                acc[i][1] = fmaf(h, wv.y, acc[i][1]);
                acc[i][2] = fmaf(h, wv.z, acc[i][2]);
                acc[i][3] = fmaf(h, wv.w, acc[i][3]);
            }
        }
    }
    #pragma unroll
    for (int i = 0; i < 8; i++)
        *(float4*)&dstBase[(base + n0 + i) * 64 + o0] =
            make_float4(acc[i][0] + bo0, acc[i][1] + bo1, acc[i][2] + bo2, acc[i][3] + bo3);
}

// ---------------- prep: zero stats + transpose weights -------------------
__global__ void k_prep(const float* __restrict__ W1, const float* __restrict__ Wk,
                       const float* __restrict__ Wq, const float* __restrict__ Wv,
                       const float* __restrict__ W3) {
    int i = blockIdx.x * 256 + threadIdx.x;
    if (i < ST_TOT) g_st[i] = 0.0;
    if (i < 5 * 4096) {
        int m = i >> 12, r = i & 4095;
        int o = r >> 6, j = r & 63;
        const float* W = (m == 0) ? W1 : (m == 1) ? Wk : (m == 2) ? Wq : (m == 3) ? Wv : W3;
        g_WT[m][j * 64 + o] = W[o * 64 + j];
    }
}

// ---------------- early: lin1 (blocks 0..255) + cvt/t-stats (256..2303) ---
__global__ void __launch_bounds__(256) k_early(const float* __restrict__ x,
                                               const int* __restrict__ ei32,
                                               const float* __restrict__ pos,
                                               const float* __restrict__ p1w,
                                               const float* __restrict__ p1b) {
    int tid = threadIdx.x;
    if (blockIdx.x < 256) {
        extern __shared__ float dyn[];
        float* sWT = dyn;
        float* sX  = dyn + 4096;
        __shared__ float ssum[64], ssq[64];
        #pragma unroll
        for (int i = tid; i < 4096; i += 256) sWT[i] = g_WT[0][i];
        if (tid < 64) { ssum[tid] = 0.f; ssq[tid] = 0.f; }
        int base = blockIdx.x * 128;
        #pragma unroll
        for (int i = tid; i < 8192; i += 256) {
            int n = i >> 6, c = i & 63;
            sX[n * 68 + c] = x[(base + n) * 64 + c];
        }
        __syncthreads();
        int o0 = (tid & 15) * 4;
        int n0 = (tid >> 4) * 8;
        float acc[8][4];
        #pragma unroll
        for (int i = 0; i < 8; i++)
            #pragma unroll
            for (int c = 0; c < 4; c++) acc[i][c] = 0.f;
        #pragma unroll
        for (int j = 0; j < 64; j += 4) {
            float4 xv[8];
            #pragma unroll
            for (int i = 0; i < 8; i++) xv[i] = *(float4*)(sX + (n0 + i) * 68 + j);
            #pragma unroll
            for (int jj = 0; jj < 4; jj++) {
                float4 wv = *(float4*)(sWT + (j + jj) * 64 + o0);
                #pragma unroll
                for (int i = 0; i < 8; i++) {
                    float h = ((const float*)&xv[i])[jj];
                    acc[i][0] = fmaf(h, wv.x, acc[i][0]);
                    acc[i][1] = fmaf(h, wv.y, acc[i][1]);
                    acc[i][2] = fmaf(h, wv.z, acc[i][2]);
                    acc[i][3] = fmaf(h, wv.w, acc[i][3]);
                }
            }
        }
        float ts[4] = {0, 0, 0, 0}, tq[4] = {0, 0, 0, 0};
        #pragma unroll
        for (int i = 0; i < 8; i++) {
            *(float4*)&g_y1[(base + n0 + i) * 64 + o0] =
                make_float4(acc[i][0], acc[i][1], acc[i][2], acc[i][3]);
            #pragma unroll
            for (int c = 0; c < 4; c++) { ts[c] += acc[i][c]; tq[c] = fmaf(acc[i][c], acc[i][c], tq[c]); }
        }
        #pragma unroll
        for (int c = 0; c < 4; c++) {
            atomicAdd(&ssum[o0 + c], ts[c]);
            atomicAdd(&ssq[o0 + c], tq[c]);
        }
        __syncthreads();
        if (tid < 64) {
            atomicAdd(&g_st[ST_BN1 + tid], (double)ssum[tid]);
            atomicAdd(&g_st[ST_BN1 + 64 + tid], (double)ssq[tid]);
        }
    } else {
        __shared__ float red[6];
        if (tid < 6) red[tid] = 0.f;
        bool is32 = (ei32[EE + 16] == 1) && (ei32[EE + 17] == 1) && (ei32[EE + 31] == 1);
        float w[9], b3[3];
        #pragma unroll
        for (int i = 0; i < 9; i++) w[i] = __ldg(&p1w[i]);
        #pragma unroll
        for (int i = 0; i < 3; i++) b3[i] = __ldg(&p1b[i]);
        __syncthreads();
        int e = (blockIdx.x - 256) * 256 + tid;
        int src = is32 ? ei32[e] : ei32[2 * e];
        g_src[e] = src;
        int d = e >> 4;
        float rx = pos[src * 3 + 0] - pos[d * 3 + 0];
        float ry = pos[src * 3 + 1] - pos[d * 3 + 1];
        float rz = pos[src * 3 + 2] - pos[d * 3 + 2];
        float t0 = fmaf(w[0], rx, fmaf(w[1], ry, fmaf(w[2], rz, b3[0])));
        float t1 = fmaf(w[3], rx, fmaf(w[4], ry, fmaf(w[5], rz, b3[1])));
        float t2 = fmaf(w[6], rx, fmaf(w[7], ry, fmaf(w[8], rz, b3[2])));
        g_t4[e] = make_float4(t0, t1, t2, 0.f);
        float s0 = t0, s1 = t1, s2 = t2, q0 = t0 * t0, q1 = t1 * t1, q2 = t2 * t2;
        #pragma unroll
        for (int m = 16; m; m >>= 1) {
            s0 += __shfl_xor_sync(0xffffffffu, s0, m);
            s1 += __shfl_xor_sync(0xffffffffu, s1, m);
            s2 += __shfl_xor_sync(0xffffffffu, s2, m);
            q0 += __shfl_xor_sync(0xffffffffu, q0, m);
            q1 += __shfl_xor_sync(0xffffffffu, q1, m);
            q2 += __shfl_xor_sync(0xffffffffu, q2, m);
        }
        if ((tid & 31) == 0) {
            atomicAdd(&red[0], s0); atomicAdd(&red[1], s1); atomicAdd(&red[2], s2);
            atomicAdd(&red[3], q0); atomicAdd(&red[4], q1); atomicAdd(&red[5], q2);
        }
        __syncthreads();
        if (tid < 6) atomicAdd(&g_st[ST_T + tid], (double)red[tid]);
    }
}

// ---------------- kq fused: one sX fill, weight reload between passes ----
__global__ void __launch_bounds__(256) k_kq(const float* __restrict__ bk,
                                            const float* __restrict__ bq,
                                            const float* __restrict__ g1,
                                            const float* __restrict__ b1) {
    extern __shared__ float dyn[];
    float* sWT = dyn;
    float* sX  = dyn + 4096;
    __shared__ float ssc[64], ssh[64];
    int tid = threadIdx.x;
    #pragma unroll
    for (int i = tid; i < 4096; i += 256) sWT[i] = g_WT[1][i];
    if (tid < 64) bn_coef(ST_BN1, 64, tid, INV_N, g1, b1, ssc[tid], ssh[tid]);
    __syncthreads();
    int base = blockIdx.x * 128;
    #pragma unroll
    for (int i = tid; i < 8192; i += 256) {
        int n = i >> 6, c = i & 63;
        float y = g_y1[(base + n) * 64 + c];
        sX[n * 68 + c] = fmaxf(fmaf(y, ssc[c], ssh[c]), 0.f);
    }
    __syncthreads();
    int o0 = (tid & 15) * 4;
    for (int m = 0; m < 2; m++) {
        const float* bias = (m == 0) ? bk : bq;
        float* dst = (m == 0) ? g_k : g_q;
        float bo0 = __ldg(&bias[o0]), bo1 = __ldg(&bias[o0 + 1]),
              bo2 = __ldg(&bias[o0 + 2]), bo3 = __ldg(&bias[o0 + 3]);
        gemm_tile(sWT, sX, dst, base, tid, bo0, bo1, bo2, bo3);
        if (m == 0) {
            __syncthreads();
            #pragma unroll
            for (int i = tid; i < 4096; i += 256) sWT[i] = g_WT[2][i];
            __syncthreads();
        }
    }
}

// ---------------- a0 stats (blocks VBLK+) + small-tile v GEMM (0..VBLK-1)
__global__ void __launch_bounds__(256, 4) k_a0v(const float* __restrict__ bv,
                                                const float* __restrict__ g1,
                                                const float* __restrict__ b1,
                                                const float* __restrict__ pbg,
                                                const float* __restrict__ pbb,
                                                const float* __restrict__ p2w,
                                                const float* __restrict__ p2b) {
    int tid = threadIdx.x;
    if (blockIdx.x < VBLK) {
        // ===== v = relu(bn1(y1)) @ Wv^T + bv  (64-node tile, 4x4 thread) ==
        extern __shared__ float dyn[];
        float* sWT = dyn;
        float* sX  = dyn + 4096;
        __shared__ float ssc[64], ssh[64];
        #pragma unroll
        for (int i = tid; i < 4096; i += 256) sWT[i] = g_WT[3][i];
        if (tid < 64) bn_coef(ST_BN1, 64, tid, INV_N, g1, b1, ssc[tid], ssh[tid]);
        __syncthreads();
        int base = blockIdx.x * 64;
        #pragma unroll
        for (int i = tid; i < 4096; i += 256) {
            int n = i >> 6, c = i & 63;
            float y = g_y1[(base + n) * 64 + c];
            sX[n * 68 + c] = fmaxf(fmaf(y, ssc[c], ssh[c]), 0.f);
        }
        __syncthreads();
        int o0 = (tid & 15) * 4;
        int n0 = (tid >> 4) * 4;
        float bo0 = __ldg(&bv[o0]), bo1 = __ldg(&bv[o0 + 1]),
              bo2 = __ldg(&bv[o0 + 2]), bo3 = __ldg(&bv[o0 + 3]);
        float acc[4][4];
        #pragma unroll
        for (int i = 0; i < 4; i++)
            #pragma unroll
            for (int c = 0; c < 4; c++) acc[i][c] = 0.f;
        #pragma unroll
        for (int j = 0; j < 64; j += 4) {
            float4 xv[4];
            #pragma unroll
            for (int i = 0; i < 4; i++) xv[i] = *(float4*)(sX + (n0 + i) * 68 + j);
            #pragma unroll
            for (int jj = 0; jj < 4; jj++) {
                float4 wv = *(float4*)(sWT + (j + jj) * 64 + o0);
                #pragma unroll
                for (int i = 0; i < 4; i++) {
                    float h = ((const float*)&xv[i])[jj];
                    acc[i][0] = fmaf(h, wv.x, acc[i][0]);
                    acc[i][1] = fmaf(h, wv.y, acc[i][1]);
                    acc[i][2] = fmaf(h, wv.z, acc[i][2]);
                    acc[i][3] = fmaf(h, wv.w, acc[i][3]);
                }
            }
        }
        #pragma unroll
        for (int i = 0; i < 4; i++)
            *(float4*)&g_v[(base + n0 + i) * 64 + o0] =
                make_float4(acc[i][0] + bo0, acc[i][1] + bo1, acc[i][2] + bo2, acc[i][3] + bo3);
        return;
    }
    // ===== a0 stats: node-blocked, 4-edge batch, late rr-shuffles =====
    __shared__ float ssum[64], ssq[64];
    __shared__ float s_tsc[3], s_tsh[3];
    if (tid < 64) { ssum[tid] = 0.f; ssq[tid] = 0.f; }
    if (tid >= 64 && tid < 67)
        bn_coef(ST_T, 3, tid - 64, INV_E, pbg, pbb, s_tsc[tid - 64], s_tsh[tid - 64]);
    int lane = tid & 31;
    int half = lane >> 4;
    int el = lane & 15;
    int c0 = el * 4;
    int hb = half << 4;
    float pw0[4], pw1[4], pw2[4], pb[4];
    #pragma unroll
    for (int i = 0; i < 4; i++) {
        pw0[i] = __ldg(&p2w[(c0 + i) * 3 + 0]);
        pw1[i] = __ldg(&p2w[(c0 + i) * 3 + 1]);
        pw2[i] = __ldg(&p2w[(c0 + i) * 3 + 2]);
        pb[i]  = __ldg(&p2b[c0 + i]);
    }
    float sums[4] = {0, 0, 0, 0}, sqs[4] = {0, 0, 0, 0};
    __syncthreads();
    float tsc[3], tsh[3];
    #pragma unroll
    for (int i = 0; i < 3; i++) { tsc[i] = s_tsc[i]; tsh[i] = s_tsh[i]; }
    int gw = ((blockIdx.x - VBLK) * 256 + tid) >> 5;
    int nw = ((gridDim.x - VBLK) * 256) >> 5;
    for (int np = gw; np < NN / 2; np += nw) {
        int node = 2 * np + half;
        int ebase = node * 16;
        int mySrc = g_src[ebase + el];
        float4 t = g_t4[ebase + el];
        float r0 = fmaxf(fmaf(t.x, tsc[0], tsh[0]), 0.f);
        float r1 = fmaxf(fmaf(t.y, tsc[1], tsh[1]), 0.f);
        float r2 = fmaxf(fmaf(t.z, tsc[2], tsh[2]), 0.f);
        float4 q4 = *(float4*)&g_q[node * 64 + c0];
        float qv[4] = {q4.x, q4.y, q4.z, q4.w};
        #pragma unroll
        for (int e2 = 0; e2 < 16; e2 += 4) {
            int s[4];
            #pragma unroll
            for (int j = 0; j < 4; j++)
                s[j] = __shfl_sync(0xffffffffu, mySrc, hb + e2 + j);
            float4 kk[4];
            #pragma unroll
            for (int j = 0; j < 4; j++) kk[j] = *(float4*)&g_k[s[j] * 64 + c0];
            #pragma unroll
            for (int j = 0; j < 4; j++) {
                float rr0 = __shfl_sync(0xffffffffu, r0, hb + e2 + j);
                float rr1 = __shfl_sync(0xffffffffu, r1, hb + e2 + j);
                float rr2 = __shfl_sync(0xffffffffu, r2, hb + e2 + j);
                float kv[4] = {kk[j].x, kk[j].y, kk[j].z, kk[j].w};
                #pragma unroll
                for (int i = 0; i < 4; i++) {
                    float dl = fmaf(rr0, pw0[i], fmaf(rr1, pw1[i],
                               fmaf(rr2, pw2[i], pb[i])));
                    float a0 = kv[i] - qv[i] + dl;
                    sums[i] += a0;
                    sqs[i] = fmaf(a0, a0, sqs[i]);
                }
            }
        }
    }
    #pragma unroll
    for (int i = 0; i < 4; i++) {
        atomicAdd(&ssum[c0 + i], sums[i]);
        atomicAdd(&ssq[c0 + i], sqs[i]);
    }
    __syncthreads();
    if (tid < 64) {
        atomicAdd(&g_st[ST_W1 + tid], (double)ssum[tid]);
        atomicAdd(&g_st[ST_W1 + 64 + tid], (double)ssq[tid]);
    }
}

// ---------------- a1: node-blocked; prefetched gathers, paired trees -----
__global__ void __launch_bounds__(256) k_a1(const float* __restrict__ pbg,
                                            const float* __restrict__ pbb,
                                            const float* __restrict__ p2w,
                                            const float* __restrict__ p2b,
                                            const float* __restrict__ wb1g,
                                            const float* __restrict__ wb1b,
                                            const float* __restrict__ w1w,
                                            const float* __restrict__ w1b) {
    __shared__ float ssum[8], ssq[8];
    __shared__ float s_tsc[3], s_tsh[3];
    __shared__ float s_scA[64], s_shA[64];
    int tid = threadIdx.x;
    if (tid < 8) { ssum[tid] = 0.f; ssq[tid] = 0.f; }
    if (tid >= 64 && tid < 67)
        bn_coef(ST_T, 3, tid - 64, INV_E, pbg, pbb, s_tsc[tid - 64], s_tsh[tid - 64]);
    if (tid < 64)
        bn_coef(ST_W1, 64, tid, INV_E, wb1g, wb1b, s_scA[tid], s_shA[tid]);
    int lane = tid & 31;
    int half = lane >> 4;
    int el = lane & 15;
    int c0 = el * 4;
    int hb = half << 4;
    float pw0[4], pw1[4], pw2[4], pb[4];
    #pragma unroll
    for (int i = 0; i < 4; i++) {
        pw0[i] = __ldg(&p2w[(c0 + i) * 3 + 0]);
        pw1[i] = __ldg(&p2w[(c0 + i) * 3 + 1]);
        pw2[i] = __ldg(&p2w[(c0 + i) * 3 + 2]);
        pb[i]  = __ldg(&p2b[c0 + i]);
    }
    float rW[8][4];
    #pragma unroll
    for (int s = 0; s < 8; s++)
        #pragma unroll
        for (int i = 0; i < 4; i++)
            rW[s][i] = __ldg(&w1w[s * 64 + c0 + i]);
    int s_mine = (lane >> 1) & 7;
    float w1bl = __ldg(&w1b[s_mine]);
    float ls = 0.f, lq = 0.f;
    __syncthreads();
    float tsc[3], tsh[3], scA[4], shA[4];
    #pragma unroll
    for (int i = 0; i < 3; i++) { tsc[i] = s_tsc[i]; tsh[i] = s_tsh[i]; }
    #pragma unroll
    for (int i = 0; i < 4; i++) { scA[i] = s_scA[c0 + i]; shA[i] = s_shA[c0 + i]; }
    int gw = (blockIdx.x * 256 + tid) >> 5;
    int nw = (gridDim.x * 256) >> 5;
    for (int np = gw; np < NN / 2; np += nw) {
        int node = 2 * np + half;
        int ebase = node * 16;
        int mySrc = g_src[ebase + el];
        float4 t = g_t4[ebase + el];
        float r0 = fmaxf(fmaf(t.x, tsc[0], tsh[0]), 0.f);
        float r1 = fmaxf(fmaf(t.y, tsc[1], tsh[1]), 0.f);
        float r2 = fmaxf(fmaf(t.z, tsc[2], tsh[2]), 0.f);
        float4 q4 = *(float4*)&g_q[node * 64 + c0];
        float qv[4] = {q4.x, q4.y, q4.z, q4.w};
        // prefetch first pair
        int srcA = __shfl_sync(0xffffffffu, mySrc, hb + 0);
        int srcB = __shfl_sync(0xffffffffu, mySrc, hb + 1);
        float4 kA = *(float4*)&g_k[srcA * 64 + c0];
        float4 kB = *(float4*)&g_k[srcB * 64 + c0];
        #pragma unroll
        for (int e2 = 0; e2 < 16; e2 += 2) {
            float4 nkA, nkB;
            if (e2 < 14) {
                int nsA = __shfl_sync(0xffffffffu, mySrc, hb + e2 + 2);
                int nsB = __shfl_sync(0xffffffffu, mySrc, hb + e2 + 3);
                nkA = *(float4*)&g_k[nsA * 64 + c0];
                nkB = *(float4*)&g_k[nsB * 64 + c0];
            }
            float rA0 = __shfl_sync(0xffffffffu, r0, hb + e2);
            float rA1 = __shfl_sync(0xffffffffu, r1, hb + e2);
            float rA2 = __shfl_sync(0xffffffffu, r2, hb + e2);
            float rB0 = __shfl_sync(0xffffffffu, r0, hb + e2 + 1);
            float rB1 = __shfl_sync(0xffffffffu, r1, hb + e2 + 1);
            float rB2 = __shfl_sync(0xffffffffu, r2, hb + e2 + 1);
            float kvA[4] = {kA.x, kA.y, kA.z, kA.w};
            float kvB[4] = {kB.x, kB.y, kB.z, kB.w};
            float pa[4], pbv[4];
            #pragma unroll
            for (int i = 0; i < 4; i++) {
                float dlA = fmaf(rA0, pw0[i], fmaf(rA1, pw1[i], fmaf(rA2, pw2[i], pb[i])));
                float a0A = kvA[i] - qv[i] + dlA;
                pa[i] = fmaxf(fmaf(a0A, scA[i], shA[i]), 0.f);
                float dlB = fmaf(rB0, pw0[i], fmaf(rB1, pw1[i], fmaf(rB2, pw2[i], pb[i])));
                float a0B = kvB[i] - qv[i] + dlB;
                pbv[i] = fmaxf(fmaf(a0B, scA[i], shA[i]), 0.f);
            }
            float accA[8], accB[8];
            #pragma unroll
            for (int s = 0; s < 8; s++) {
                accA[s] = fmaf(pa[0], rW[s][0], fmaf(pa[1], rW[s][1],
                          fmaf(pa[2], rW[s][2], pa[3] * rW[s][3])));
                accB[s] = fmaf(pbv[0], rW[s][0], fmaf(pbv[1], rW[s][1],
                          fmaf(pbv[2], rW[s][2], pbv[3] * rW[s][3])));
            }
            #pragma unroll
            for (int s = 0; s < 8; s++) {
                accA[s] += __shfl_xor_sync(0xffffffffu, accA[s], 8);
                accB[s] += __shfl_xor_sync(0xffffffffu, accB[s], 8);
            }
            bool hb3 = (lane & 8) != 0;
            float c4A[4], c4B[4];
            #pragma unroll
            for (int i = 0; i < 4; i++) {
                c4A[i] = hb3 ? accA[4 + i] : accA[i];
                c4B[i] = hb3 ? accB[4 + i] : accB[i];
            }
            #pragma unroll
            for (int i = 0; i < 4; i++) {
                c4A[i] += __shfl_xor_sync(0xffffffffu, c4A[i], 4);
                c4B[i] += __shfl_xor_sync(0xffffffffu, c4B[i], 4);
            }
            bool hb2 = (lane & 4) != 0;
            float c2aA = hb2 ? c4A[2] : c4A[0];
            float c2bA = hb2 ? c4A[3] : c4A[1];
            float c2aB = hb2 ? c4B[2] : c4B[0];
            float c2bB = hb2 ? c4B[3] : c4B[1];
            c2aA += __shfl_xor_sync(0xffffffffu, c2aA, 2);
            c2bA += __shfl_xor_sync(0xffffffffu, c2bA, 2);
            c2aB += __shfl_xor_sync(0xffffffffu, c2aB, 2);
            c2bB += __shfl_xor_sync(0xffffffffu, c2bB, 2);
            bool hb1 = (lane & 2) != 0;
            float c1A = hb1 ? c2bA : c2aA;
            float c1B = hb1 ? c2bB : c2aB;
            c1A += __shfl_xor_sync(0xffffffffu, c1A, 1);
            c1B += __shfl_xor_sync(0xffffffffu, c1B, 1);
            if ((lane & 1) == 0) {
                float fA = c1A + w1bl;
                float fB = c1B + w1bl;
                g_a1[(ebase + e2) * 8 + s_mine] = fA;
                g_a1[(ebase + e2 + 1) * 8 + s_mine] = fB;
                ls += fA + fB;
                lq = fmaf(fA, fA, lq);
                lq = fmaf(fB, fB, lq);
            }
            kA = nkA; kB = nkB;
        }
    }
    if ((lane & 1) == 0) {
        atomicAdd(&ssum[s_mine], ls);
        atomicAdd(&ssq[s_mine], lq);
    }
    __syncthreads();
    if (tid < 8) {
        atomicAdd(&g_st[ST_W2 + tid], (double)ssum[tid]);
        atomicAdd(&g_st[ST_W2 + 8 + tid], (double)ssq[tid]);
    }
}

// ---------------- aggregate: a2 + softmax + weighted sum; bn2 stats ------
__global__ void __launch_bounds__(256) k_aggr(const float* __restrict__ pbg,
                                              const float* __restrict__ pbb,
                                              const float* __restrict__ p2w,
                                              const float* __restrict__ p2b,
                                              const float* __restrict__ wb2g,
                                              const float* __restrict__ wb2b,
                                              const float* __restrict__ w2w,
                                              const float* __restrict__ w2b) {
    __shared__ float sAttn[8][2][16][8];
    __shared__ float sR[8][2][16][3];
    __shared__ int   sSrc[8][2][16];
    __shared__ float sRagg[8][2][8][3];
    __shared__ float sp2[64][4];
    __shared__ float sw2[64];
    __shared__ float sw2b[8];
    __shared__ float ssum[64], ssq[64];
    __shared__ float s_tsc[3], s_tsh[3], s_sc2[8], s_sh2[8];

    int tid = threadIdx.x;
    int warp = tid >> 5, lane = tid & 31;
    {
        int c = tid >> 2, j = tid & 3;
        sp2[c][j] = (j < 3) ? p2w[c * 3 + j] : p2b[c];
    }
    if (tid < 64) { sw2[tid] = w2w[tid]; ssum[tid] = 0.f; ssq[tid] = 0.f; }
    if (tid >= 64 && tid < 72) sw2b[tid - 64] = w2b[tid - 64];
    if (tid >= 72 && tid < 75)
        bn_coef(ST_T, 3, tid - 72, INV_E, pbg, pbb, s_tsc[tid - 72], s_tsh[tid - 72]);
    if (tid >= 80 && tid < 88)
        bn_coef(ST_W2, 8, tid - 80, INV_E, wb2g, wb2b, s_sc2[tid - 80], s_sh2[tid - 80]);
    __syncthreads();

    int nodeBase = blockIdx.x * 16 + warp * 2;
    int sub = lane >> 4, el = lane & 15;
    int node = nodeBase + sub;
    int e = node * 16 + el;
    int src = g_src[e];
    sSrc[warp][sub][el] = src;
    float4 t = g_t4[e];
    float r0 = fmaxf(fmaf(t.x, s_tsc[0], s_tsh[0]), 0.f);
    float r1 = fmaxf(fmaf(t.y, s_tsc[1], s_tsh[1]), 0.f);
    float r2 = fmaxf(fmaf(t.z, s_tsc[2], s_tsh[2]), 0.f);
    sR[warp][sub][el][0] = r0; sR[warp][sub][el][1] = r1; sR[warp][sub][el][2] = r2;

    float4 a1lo = *(float4*)&g_a1[e * 8];
    float4 a1hi = *(float4*)&g_a1[e * 8 + 4];
    float av[8] = {a1lo.x, a1lo.y, a1lo.z, a1lo.w, a1hi.x, a1hi.y, a1hi.z, a1hi.w};
    float pbn[8];
    #pragma unroll
    for (int s = 0; s < 8; s++)
        pbn[s] = fmaxf(fmaf(av[s], s_sc2[s], s_sh2[s]), 0.f);
    #pragma unroll
    for (int s = 0; s < 8; s++) {
        float a2 = sw2b[s];
        #pragma unroll
        for (int s2 = 0; s2 < 8; s2++) a2 = fmaf(pbn[s2], sw2[s * 8 + s2], a2);
        float mx = a2;
        #pragma unroll
        for (int m = 8; m; m >>= 1) mx = fmaxf(mx, __shfl_xor_sync(0xffffffffu, mx, m));
        float ex = __expf(a2 - mx);
        float sm = ex;
        #pragma unroll
        for (int m = 8; m; m >>= 1) sm += __shfl_xor_sync(0xffffffffu, sm, m);
        sAttn[warp][sub][el][s] = ex / sm;
    }
    __syncwarp();

    if (lane < 24) {
        int g = lane / 3, comp = lane % 3;
        #pragma unroll
        for (int sb = 0; sb < 2; sb++) {
            float rag = 0.f;
            #pragma unroll
            for (int e2 = 0; e2 < 16; e2++)
                rag = fmaf(sAttn[warp][sb][e2][g], sR[warp][sb][e2][comp], rag);
            sRagg[warp][sb][g][comp] = rag;
        }
    }
    __syncwarp();

    int gl = lane & 7;
    int c0 = lane, c1 = lane + 32;
    #pragma unroll
    for (int sb = 0; sb < 2; sb++) {
        int nd = nodeBase + sb;
        float rag0 = sRagg[warp][sb][gl][0];
        float rag1 = sRagg[warp][sb][gl][1];
        float rag2 = sRagg[warp][sb][gl][2];
        float acc0 = fmaf(sp2[c0][0], rag0, fmaf(sp2[c0][1], rag1,
                     fmaf(sp2[c0][2], rag2, sp2[c0][3])));
        float acc1 = fmaf(sp2[c1][0], rag0, fmaf(sp2[c1][1], rag1,
                     fmaf(sp2[c1][2], rag2, sp2[c1][3])));
        #pragma unroll
        for (int e2 = 0; e2 < 16; e2++) {
            float at = sAttn[warp][sb][e2][gl];
            const float* vr = &g_v[sSrc[warp][sb][e2] * 64];
            acc0 = fmaf(at, vr[c0], acc0);
            acc1 = fmaf(at, vr[c1], acc1);
        }
        g_out[nd * 64 + c0] = acc0;
        g_out[nd * 64 + c1] = acc1;
        atomicAdd(&ssum[c0], acc0); atomicAdd(&ssq[c0], acc0 * acc0);
        atomicAdd(&ssum[c1], acc1); atomicAdd(&ssq[c1], acc1 * acc1);
    }
    __syncthreads();
    if (tid < 64) {
        atomicAdd(&g_st[ST_BN2 + tid], (double)ssum[tid]);
        atomicAdd(&g_st[ST_BN2 + 64 + tid], (double)ssq[tid]);
    }
}

// ---------------- GEMM 3: y3 = relu(bn2(out)) @ W3^T; bn3 stats ----------
__global__ void __launch_bounds__(256) k_lin3(const float* __restrict__ g2,
                                              const float* __restrict__ b2) {
    extern __shared__ float dyn[];
    float* sWT = dyn;
    float* sX  = dyn + 4096;
    __shared__ float ssc[64], ssh[64];
    __shared__ float ssum[64], ssq[64];
    int tid = threadIdx.x;
    #pragma unroll
    for (int i = tid; i < 4096; i += 256) sWT[i] = g_WT[4][i];
    if (tid < 64) {
        bn_coef(ST_BN2, 64, tid, INV_N, g2, b2, ssc[tid], ssh[tid]);
        ssum[tid] = 0.f; ssq[tid] = 0.f;
    }
    __syncthreads();
    int base = blockIdx.x * 128;
    #pragma unroll
    for (int i = tid; i < 8192; i += 256) {
        int n = i >> 6, c = i & 63;
        float y = g_out[(base + n) * 64 + c];
        sX[n * 68 + c] = fmaxf(fmaf(y, ssc[c], ssh[c]), 0.f);
    }
    __syncthreads();
    int o0 = (tid & 15) * 4;
    int n0 = (tid >> 4) * 8;
    float acc[8][4];
    #pragma unroll
    for (int i = 0; i < 8; i++)
        #pragma unroll
        for (int c = 0; c < 4; c++) acc[i][c] = 0.f;
    #pragma unroll
    for (int j = 0; j < 64; j += 4) {
        float4 xv[8];
        #pragma unroll
        for (int i = 0; i < 8; i++) xv[i] = *(float4*)(sX + (n0 + i) * 68 + j);
        #pragma unroll
        for (int jj = 0; jj < 4; jj++) {
            float4 wv = *(float4*)(sWT + (j + jj) * 64 + o0);
            #pragma unroll
            for (int i = 0; i < 8; i++) {
                float h = ((const float*)&xv[i])[jj];
                acc[i][0] = fmaf(h, wv.x, acc[i][0]);
                acc[i][1] = fmaf(h, wv.y, acc[i][1]);
                acc[i][2] = fmaf(h, wv.z, acc[i][2]);
                acc[i][3] = fmaf(h, wv.w, acc[i][3]);
            }
        }
    }
    float ts[4] = {0, 0, 0, 0}, tq[4] = {0, 0, 0, 0};
    #pragma unroll
    for (int i = 0; i < 8; i++) {
        *(float4*)&g_y3[(base + n0 + i) * 64 + o0] =
            make_float4(acc[i][0], acc[i][1], acc[i][2], acc[i][3]);
        #pragma unroll
        for (int c = 0; c < 4; c++) { ts[c] += acc[i][c]; tq[c] = fmaf(acc[i][c], acc[i][c], tq[c]); }
    }
    #pragma unroll
    for (int c = 0; c < 4; c++) {
        atomicAdd(&ssum[o0 + c], ts[c]);
        atomicAdd(&ssq[o0 + c], tq[c]);
    }
    __syncthreads();
    if (tid < 64) {
        atomicAdd(&g_st[ST_BN3 + tid], (double)ssum[tid]);
        atomicAdd(&g_st[ST_BN3 + 64 + tid], (double)ssq[tid]);
    }
}

// ---------------- final: relu(bn3(y3) + x) --------------------------------
__global__ void __launch_bounds__(256) k_final(const float* __restrict__ x,
                                               const float* __restrict__ g3,
                                               const float* __restrict__ b3,
                                               float* __restrict__ out) {
    __shared__ float ssc[64], ssh[64];
    int tid = threadIdx.x;
    if (tid < 64) bn_coef(ST_BN3, 64, tid, INV_N, g3, b3, ssc[tid], ssh[tid]);
    __syncthreads();
    int gid = blockIdx.x * 256 + tid;
    int i = gid * 4;
    int c0 = i & 63;
    float4 y = *(float4*)&g_y3[i];
    float4 xv = *(const float4*)&x[i];
    float4 r;
    r.x = fmaxf(fmaf(y.x, ssc[c0 + 0], ssh[c0 + 0]) + xv.x, 0.f);
    r.y = fmaxf(fmaf(y.y, ssc[c0 + 1], ssh[c0 + 1]) + xv.y, 0.f);
    r.z = fmaxf(fmaf(y.z, ssc[c0 + 2], ssh[c0 + 2]) + xv.z, 0.f);
    r.w = fmaxf(fmaf(y.w, ssc[c0 + 3], ssh[c0 + 3]) + xv.w, 0.f);
    *(float4*)&out[i] = r;
}

// ---------------- launch ---------------------------------------------------
extern "C" void kernel_launch(void* const* d_in, const int* in_sizes, int n_in,
                              void* d_out, int out_size) {
    const float* pos  = (const float*)d_in[0];
    const float* x    = (const float*)d_in[1];
    const float* W1   = (const float*)d_in[2];
    const float* Wk   = (const float*)d_in[3];
    const float* bk   = (const float*)d_in[4];
    const float* Wq   = (const float*)d_in[5];
    const float* bq   = (const float*)d_in[6];
    const float* Wv   = (const float*)d_in[7];
    const float* bv   = (const float*)d_in[8];
    const float* p1w  = (const float*)d_in[9];
    const float* p1b  = (const float*)d_in[10];
    const float* pbg  = (const float*)d_in[11];
    const float* pbb  = (const float*)d_in[12];
    const float* p2w  = (const float*)d_in[13];
    const float* p2b  = (const float*)d_in[14];
    const float* wb1g = (const float*)d_in[15];
    const float* wb1b = (const float*)d_in[16];
    const float* w1w  = (const float*)d_in[17];
    const float* w1b  = (const float*)d_in[18];
    const float* wb2g = (const float*)d_in[19];
    const float* wb2b = (const float*)d_in[20];
    const float* w2w  = (const float*)d_in[21];
    const float* w2b  = (const float*)d_in[22];
    const float* W3   = (const float*)d_in[23];
    const float* g1   = (const float*)d_in[24];
    const float* b1   = (const float*)d_in[25];
    const float* g2   = (const float*)d_in[26];
    const float* b2   = (const float*)d_in[27];
    const float* g3   = (const float*)d_in[28];
    const float* b3   = (const float*)d_in[29];
    const int*   ei   = (const int*)d_in[30];
    float* out = (float*)d_out;

    cudaFuncSetAttribute(k_early, cudaFuncAttributeMaxDynamicSharedMemorySize, GEMM_SMEM);
    cudaFuncSetAttribute(k_lin3,  cudaFuncAttributeMaxDynamicSharedMemorySize, GEMM_SMEM);
    cudaFuncSetAttribute(k_kq,    cudaFuncAttributeMaxDynamicSharedMemorySize, GEMM_SMEM);
    cudaFuncSetAttribute(k_a0v,   cudaFuncAttributeMaxDynamicSharedMemorySize, A0V_SMEM);

    k_prep<<<80, 256>>>(W1, Wk, Wq, Wv, W3);
    k_early<<<256 + EE / 256, 256, GEMM_SMEM>>>(x, ei, pos, p1w, p1b);
    k_kq<<<NN / 128, 256, GEMM_SMEM>>>(bk, bq, g1, b1);
    k_a0v<<<VBLK + 1184, 256, A0V_SMEM>>>(bv, g1, b1, pbg, pbb, p2w, p2b);
    k_a1<<<1184, 256>>>(pbg, pbb, p2w, p2b, wb1g, wb1b, w1w, w1b);
    k_aggr<<<NN / 16, 256>>>(pbg, pbb, p2w, p2b, wb2g, wb2b, w2w, w2b);
    k_lin3<<<NN / 128, 256, GEMM_SMEM>>>(g2, b2);
    k_final<<<(NN * CC) / 1024, 256>>>(x, g3, b3, out);
}

// round 15
// speedup vs baseline: 1.0687x; 1.0687x over previous
#include <cuda_runtime.h>

#define NN 32768
#define CC 64
#define KK 16
#define SS 8
#define EE (NN * KK)
#define EPS 1e-5f

// ---------------- scratch ----------------
__device__ float g_y1[NN * CC];
__device__ float g_k[NN * CC];
__device__ float g_q[NN * CC];
__device__ float g_v[NN * CC];
__device__ float g_a1[EE * SS];
__device__ float g_out[NN * CC];
__device__ float g_y3[NN * CC];
__device__ int   g_src[EE];
__device__ float4 g_t4[EE];
__device__ float g_WT[5][4096];   // [j*64+o]; 0=W1,1=Wk,2=Wq,3=Wv,4=W3

#define ST_BN1 0
#define ST_T   128
#define ST_W1  134
#define ST_W2  262
#define ST_BN2 278
#define ST_BN3 406
#define ST_TOT 534
__device__ double g_st[ST_TOT];

#define INV_N  (1.0 / (double)NN)
#define INV_E  (1.0 / (double)EE)

// dynamic smem: weights (4096) + X tile (128*68)
#define GEMM_SMEM ((4096 + 128 * 68) * 4)
#define A0_EDGE_BLOCKS 1072

__device__ __forceinline__ void bn_coef(int off, int nch, int c, double inv_cnt,
                                        const float* __restrict__ g,
                                        const float* __restrict__ b,
                                        float& scale, float& shift) {
    double m = g_st[off + c] * inv_cnt;
    double v = g_st[off + nch + c] * inv_cnt - m * m;
    float rs = rsqrtf(fmaxf((float)v, 0.f) + EPS);
    scale = rs * __ldg(&g[c]);
    shift = __ldg(&b[c]) - (float)m * scale;
}

// shared GEMM body: 128-node tile, 8 nodes x 4 outputs per thread
__device__ __forceinline__ void gemm_tile(const float* sWT, const float* sX,
                                          float* dstBase, int base, int tid,
                                          float bo0, float bo1, float bo2, float bo3) {
    int o0 = (tid & 15) * 4;
    int n0 = (tid >> 4) * 8;
    float acc[8][4];
    #pragma unroll
    for (int i = 0; i < 8; i++)
        #pragma unroll
        for (int c = 0; c < 4; c++) acc[i][c] = 0.f;
    #pragma unroll
    for (int j = 0; j < 64; j += 4) {
        float4 xv[8];
        #pragma unroll
        for (int i = 0; i < 8; i++) xv[i] = *(float4*)(sX + (n0 + i) * 68 + j);
        #pragma unroll
        for (int jj = 0; jj < 4; jj++) {
            float4 wv = *(float4*)(sWT + (j + jj) * 64 + o0);
            #pragma unroll
            for (int i = 0; i < 8; i++) {
                float h = ((const float*)&xv[i])[jj];
                acc[i][0] = fmaf(h, wv.x, acc[i][0]);
                acc[i][1] = fmaf(h, wv.y, acc[i][1]);
                acc[i][2] = fmaf(h, wv.z, acc[i][2]);
                acc[i][3] = fmaf(h, wv.w, acc[i][3]);
            }
        }
    }
    #pragma unroll
    for (int i = 0; i < 8; i++)
        *(float4*)&dstBase[(base + n0 + i) * 64 + o0] =
            make_float4(acc[i][0] + bo0, acc[i][1] + bo1, acc[i][2] + bo2, acc[i][3] + bo3);
}

// ---------------- prep: zero stats + transpose weights -------------------
__global__ void k_prep(const float* __restrict__ W1, const float* __restrict__ Wk,
                       const float* __restrict__ Wq, const float* __restrict__ Wv,
                       const float* __restrict__ W3) {
    int i = blockIdx.x * 256 + threadIdx.x;
    if (i < ST_TOT) g_st[i] = 0.0;
    if (i < 5 * 4096) {
        int m = i >> 12, r = i & 4095;
        int o = r >> 6, j = r & 63;
        const float* W = (m == 0) ? W1 : (m == 1) ? Wk : (m == 2) ? Wq : (m == 3) ? Wv : W3;
        g_WT[m][j * 64 + o] = W[o * 64 + j];
    }
}

// ---------------- early: lin1 (blocks 0..255) + cvt/t-stats (256..2303) ---
__global__ void __launch_bounds__(256) k_early(const float* __restrict__ x,
                                               const int* __restrict__ ei32,
                                               const float* __restrict__ pos,
                                               const float* __restrict__ p1w,
                                               const float* __restrict__ p1b) {
    int tid = threadIdx.x;
    if (blockIdx.x < 256) {
        extern __shared__ float dyn[];
        float* sWT = dyn;
        float* sX  = dyn + 4096;
        __shared__ float ssum[64], ssq[64];
        #pragma unroll
        for (int i = tid; i < 4096; i += 256) sWT[i] = g_WT[0][i];
        if (tid < 64) { ssum[tid] = 0.f; ssq[tid] = 0.f; }
        int base = blockIdx.x * 128;
        #pragma unroll
        for (int i = tid; i < 8192; i += 256) {
            int n = i >> 6, c = i & 63;
            sX[n * 68 + c] = x[(base + n) * 64 + c];
        }
        __syncthreads();
        int o0 = (tid & 15) * 4;
        int n0 = (tid >> 4) * 8;
        float acc[8][4];
        #pragma unroll
        for (int i = 0; i < 8; i++)
            #pragma unroll
            for (int c = 0; c < 4; c++) acc[i][c] = 0.f;
        #pragma unroll
        for (int j = 0; j < 64; j += 4) {
            float4 xv[8];
            #pragma unroll
            for (int i = 0; i < 8; i++) xv[i] = *(float4*)(sX + (n0 + i) * 68 + j);
            #pragma unroll
            for (int jj = 0; jj < 4; jj++) {
                float4 wv = *(float4*)(sWT + (j + jj) * 64 + o0);
                #pragma unroll
                for (int i = 0; i < 8; i++) {
                    float h = ((const float*)&xv[i])[jj];
                    acc[i][0] = fmaf(h, wv.x, acc[i][0]);
                    acc[i][1] = fmaf(h, wv.y, acc[i][1]);
                    acc[i][2] = fmaf(h, wv.z, acc[i][2]);
                    acc[i][3] = fmaf(h, wv.w, acc[i][3]);
                }
            }
        }
        float ts[4] = {0, 0, 0, 0}, tq[4] = {0, 0, 0, 0};
        #pragma unroll
        for (int i = 0; i < 8; i++) {
            *(float4*)&g_y1[(base + n0 + i) * 64 + o0] =
                make_float4(acc[i][0], acc[i][1], acc[i][2], acc[i][3]);
            #pragma unroll
            for (int c = 0; c < 4; c++) { ts[c] += acc[i][c]; tq[c] = fmaf(acc[i][c], acc[i][c], tq[c]); }
        }
        #pragma unroll
        for (int c = 0; c < 4; c++) {
            atomicAdd(&ssum[o0 + c], ts[c]);
            atomicAdd(&ssq[o0 + c], tq[c]);
        }
        __syncthreads();
        if (tid < 64) {
            atomicAdd(&g_st[ST_BN1 + tid], (double)ssum[tid]);
            atomicAdd(&g_st[ST_BN1 + 64 + tid], (double)ssq[tid]);
        }
    } else {
        __shared__ float red[6];
        if (tid < 6) red[tid] = 0.f;
        bool is32 = (ei32[EE + 16] == 1) && (ei32[EE + 17] == 1) && (ei32[EE + 31] == 1);
        float w[9], b3[3];
        #pragma unroll
        for (int i = 0; i < 9; i++) w[i] = __ldg(&p1w[i]);
        #pragma unroll
        for (int i = 0; i < 3; i++) b3[i] = __ldg(&p1b[i]);
        __syncthreads();
        int e = (blockIdx.x - 256) * 256 + tid;
        int src = is32 ? ei32[e] : ei32[2 * e];
        g_src[e] = src;
        int d = e >> 4;
        float rx = pos[src * 3 + 0] - pos[d * 3 + 0];
        float ry = pos[src * 3 + 1] - pos[d * 3 + 1];
        float rz = pos[src * 3 + 2] - pos[d * 3 + 2];
        float t0 = fmaf(w[0], rx, fmaf(w[1], ry, fmaf(w[2], rz, b3[0])));
        float t1 = fmaf(w[3], rx, fmaf(w[4], ry, fmaf(w[5], rz, b3[1])));
        float t2 = fmaf(w[6], rx, fmaf(w[7], ry, fmaf(w[8], rz, b3[2])));
        g_t4[e] = make_float4(t0, t1, t2, 0.f);
        float s0 = t0, s1 = t1, s2 = t2, q0 = t0 * t0, q1 = t1 * t1, q2 = t2 * t2;
        #pragma unroll
        for (int m = 16; m; m >>= 1) {
            s0 += __shfl_xor_sync(0xffffffffu, s0, m);
            s1 += __shfl_xor_sync(0xffffffffu, s1, m);
            s2 += __shfl_xor_sync(0xffffffffu, s2, m);
            q0 += __shfl_xor_sync(0xffffffffu, q0, m);
            q1 += __shfl_xor_sync(0xffffffffu, q1, m);
            q2 += __shfl_xor_sync(0xffffffffu, q2, m);
        }
        if ((tid & 31) == 0) {
            atomicAdd(&red[0], s0); atomicAdd(&red[1], s1); atomicAdd(&red[2], s2);
            atomicAdd(&red[3], q0); atomicAdd(&red[4], q1); atomicAdd(&red[5], q2);
        }
        __syncthreads();
        if (tid < 6) atomicAdd(&g_st[ST_T + tid], (double)red[tid]);
    }
}

// ---------------- kq fused: one sX fill, weight reload between passes ----
__global__ void __launch_bounds__(256) k_kq(const float* __restrict__ bk,
                                            const float* __restrict__ bq,
                                            const float* __restrict__ g1,
                                            const float* __restrict__ b1) {
    extern __shared__ float dyn[];
    float* sWT = dyn;
    float* sX  = dyn + 4096;
    __shared__ float ssc[64], ssh[64];
    int tid = threadIdx.x;
    #pragma unroll
    for (int i = tid; i < 4096; i += 256) sWT[i] = g_WT[1][i];
    if (tid < 64) bn_coef(ST_BN1, 64, tid, INV_N, g1, b1, ssc[tid], ssh[tid]);
    __syncthreads();
    int base = blockIdx.x * 128;
    #pragma unroll
    for (int i = tid; i < 8192; i += 256) {
        int n = i >> 6, c = i & 63;
        float y = g_y1[(base + n) * 64 + c];
        sX[n * 68 + c] = fmaxf(fmaf(y, ssc[c], ssh[c]), 0.f);
    }
    __syncthreads();
    int o0 = (tid & 15) * 4;
    for (int m = 0; m < 2; m++) {
        const float* bias = (m == 0) ? bk : bq;
        float* dst = (m == 0) ? g_k : g_q;
        float bo0 = __ldg(&bias[o0]), bo1 = __ldg(&bias[o0 + 1]),
              bo2 = __ldg(&bias[o0 + 2]), bo3 = __ldg(&bias[o0 + 3]);
        gemm_tile(sWT, sX, dst, base, tid, bo0, bo1, bo2, bo3);
        if (m == 0) {
            __syncthreads();
            #pragma unroll
            for (int i = tid; i < 4096; i += 256) sWT[i] = g_WT[2][i];
            __syncthreads();
        }
    }
}

// ---------------- a0 stats (blocks 256+) co-scheduled with v GEMM (0..255)
__global__ void __launch_bounds__(256) k_a0v(const float* __restrict__ bv,
                                             const float* __restrict__ g1,
                                             const float* __restrict__ b1,
                                             const float* __restrict__ pbg,
                                             const float* __restrict__ pbb,
                                             const float* __restrict__ p2w,
                                             const float* __restrict__ p2b) {
    int tid = threadIdx.x;
    if (blockIdx.x < 256) {
        // ===== v = relu(bn1(y1)) @ Wv^T + bv =====
        extern __shared__ float dyn[];
        float* sWT = dyn;
        float* sX  = dyn + 4096;
        __shared__ float ssc[64], ssh[64];
        #pragma unroll
        for (int i = tid; i < 4096; i += 256) sWT[i] = g_WT[3][i];
        if (tid < 64) bn_coef(ST_BN1, 64, tid, INV_N, g1, b1, ssc[tid], ssh[tid]);
        __syncthreads();
        int base = blockIdx.x * 128;
        #pragma unroll
        for (int i = tid; i < 8192; i += 256) {
            int n = i >> 6, c = i & 63;
            float y = g_y1[(base + n) * 64 + c];
            sX[n * 68 + c] = fmaxf(fmaf(y, ssc[c], ssh[c]), 0.f);
        }
        __syncthreads();
        int o0 = (tid & 15) * 4;
        float bo0 = __ldg(&bv[o0]), bo1 = __ldg(&bv[o0 + 1]),
              bo2 = __ldg(&bv[o0 + 2]), bo3 = __ldg(&bv[o0 + 3]);
        gemm_tile(sWT, sX, g_v, base, tid, bo0, bo1, bo2, bo3);
        return;
    }
    // ===== a0 stats: node-blocked, 4-edge batch, late rr-shuffles =====
    __shared__ float ssum[64], ssq[64];
    __shared__ float s_tsc[3], s_tsh[3];
    if (tid < 64) { ssum[tid] = 0.f; ssq[tid] = 0.f; }
    if (tid >= 64 && tid < 67)
        bn_coef(ST_T, 3, tid - 64, INV_E, pbg, pbb, s_tsc[tid - 64], s_tsh[tid - 64]);
    int lane = tid & 31;
    int half = lane >> 4;
    int el = lane & 15;
    int c0 = el * 4;
    int hb = half << 4;
    float pw0[4], pw1[4], pw2[4], pb[4];
    #pragma unroll
    for (int i = 0; i < 4; i++) {
        pw0[i] = __ldg(&p2w[(c0 + i) * 3 + 0]);
        pw1[i] = __ldg(&p2w[(c0 + i) * 3 + 1]);
        pw2[i] = __ldg(&p2w[(c0 + i) * 3 + 2]);
        pb[i]  = __ldg(&p2b[c0 + i]);
    }
    float sums[4] = {0, 0, 0, 0}, sqs[4] = {0, 0, 0, 0};
    __syncthreads();
    float tsc[3], tsh[3];
    #pragma unroll
    for (int i = 0; i < 3; i++) { tsc[i] = s_tsc[i]; tsh[i] = s_tsh[i]; }
    int gw = ((blockIdx.x - 256) * 256 + tid) >> 5;
    int nw = ((gridDim.x - 256) * 256) >> 5;
    for (int np = gw; np < NN / 2; np += nw) {
        int node = 2 * np + half;
        int ebase = node * 16;
        int mySrc = g_src[ebase + el];
        float4 t = g_t4[ebase + el];
        float r0 = fmaxf(fmaf(t.x, tsc[0], tsh[0]), 0.f);
        float r1 = fmaxf(fmaf(t.y, tsc[1], tsh[1]), 0.f);
        float r2 = fmaxf(fmaf(t.z, tsc[2], tsh[2]), 0.f);
        float4 q4 = *(float4*)&g_q[node * 64 + c0];
        float qv[4] = {q4.x, q4.y, q4.z, q4.w};
        #pragma unroll
        for (int e2 = 0; e2 < 16; e2 += 4) {
            int s[4];
            #pragma unroll
            for (int j = 0; j < 4; j++)
                s[j] = __shfl_sync(0xffffffffu, mySrc, hb + e2 + j);
            float4 kk[4];
            #pragma unroll
            for (int j = 0; j < 4; j++) kk[j] = *(float4*)&g_k[s[j] * 64 + c0];
            #pragma unroll
            for (int j = 0; j < 4; j++) {
                float rr0 = __shfl_sync(0xffffffffu, r0, hb + e2 + j);
                float rr1 = __shfl_sync(0xffffffffu, r1, hb + e2 + j);
                float rr2 = __shfl_sync(0xffffffffu, r2, hb + e2 + j);
                float kv[4] = {kk[j].x, kk[j].y, kk[j].z, kk[j].w};
                #pragma unroll
                for (int i = 0; i < 4; i++) {
                    float dl = fmaf(rr0, pw0[i], fmaf(rr1, pw1[i],
                               fmaf(rr2, pw2[i], pb[i])));
                    float a0 = kv[i] - qv[i] + dl;
                    sums[i] += a0;
                    sqs[i] = fmaf(a0, a0, sqs[i]);
                }
            }
        }
    }
    #pragma unroll
    for (int i = 0; i < 4; i++) {
        atomicAdd(&ssum[c0 + i], sums[i]);
        atomicAdd(&ssq[c0 + i], sqs[i]);
    }
    __syncthreads();
    if (tid < 64) {
        atomicAdd(&g_st[ST_W1 + tid], (double)ssum[tid]);
        atomicAdd(&g_st[ST_W1 + 64 + tid], (double)ssq[tid]);
    }
}

// ---------------- a1: node-blocked; prefetched gathers, paired trees -----
__global__ void __launch_bounds__(256) k_a1(const float* __restrict__ pbg,
                                            const float* __restrict__ pbb,
                                            const float* __restrict__ p2w,
                                            const float* __restrict__ p2b,
                                            const float* __restrict__ wb1g,
                                            const float* __restrict__ wb1b,
                                            const float* __restrict__ w1w,
                                            const float* __restrict__ w1b) {
    __shared__ float ssum[8], ssq[8];
    __shared__ float s_tsc[3], s_tsh[3];
    __shared__ float s_scA[64], s_shA[64];
    int tid = threadIdx.x;
    if (tid < 8) { ssum[tid] = 0.f; ssq[tid] = 0.f; }
    if (tid >= 64 && tid < 67)
        bn_coef(ST_T, 3, tid - 64, INV_E, pbg, pbb, s_tsc[tid - 64], s_tsh[tid - 64]);
    if (tid < 64)
        bn_coef(ST_W1, 64, tid, INV_E, wb1g, wb1b, s_scA[tid], s_shA[tid]);
    int lane = tid & 31;
    int half = lane >> 4;
    int el = lane & 15;
    int c0 = el * 4;
    int hb = half << 4;
    float pw0[4], pw1[4], pw2[4], pb[4];
    #pragma unroll
    for (int i = 0; i < 4; i++) {
        pw0[i] = __ldg(&p2w[(c0 + i) * 3 + 0]);
        pw1[i] = __ldg(&p2w[(c0 + i) * 3 + 1]);
        pw2[i] = __ldg(&p2w[(c0 + i) * 3 + 2]);
        pb[i]  = __ldg(&p2b[c0 + i]);
    }
    float rW[8][4];
    #pragma unroll
    for (int s = 0; s < 8; s++)
        #pragma unroll
        for (int i = 0; i < 4; i++)
            rW[s][i] = __ldg(&w1w[s * 64 + c0 + i]);
    int s_mine = (lane >> 1) & 7;
    float w1bl = __ldg(&w1b[s_mine]);
    float ls = 0.f, lq = 0.f;
    __syncthreads();
    float tsc[3], tsh[3], scA[4], shA[4];
    #pragma unroll
    for (int i = 0; i < 3; i++) { tsc[i] = s_tsc[i]; tsh[i] = s_tsh[i]; }
    #pragma unroll
    for (int i = 0; i < 4; i++) { scA[i] = s_scA[c0 + i]; shA[i] = s_shA[c0 + i]; }
    int gw = (blockIdx.x * 256 + tid) >> 5;
    int nw = (gridDim.x * 256) >> 5;
    for (int np = gw; np < NN / 2; np += nw) {
        int node = 2 * np + half;
        int ebase = node * 16;
        int mySrc = g_src[ebase + el];
        float4 t = g_t4[ebase + el];
        float r0 = fmaxf(fmaf(t.x, tsc[0], tsh[0]), 0.f);
        float r1 = fmaxf(fmaf(t.y, tsc[1], tsh[1]), 0.f);
        float r2 = fmaxf(fmaf(t.z, tsc[2], tsh[2]), 0.f);
        float4 q4 = *(float4*)&g_q[node * 64 + c0];
        float qv[4] = {q4.x, q4.y, q4.z, q4.w};
        // prefetch first pair
        int srcA = __shfl_sync(0xffffffffu, mySrc, hb + 0);
        int srcB = __shfl_sync(0xffffffffu, mySrc, hb + 1);
        float4 kA = *(float4*)&g_k[srcA * 64 + c0];
        float4 kB = *(float4*)&g_k[srcB * 64 + c0];
        #pragma unroll
        for (int e2 = 0; e2 < 16; e2 += 2) {
            float4 nkA, nkB;
            if (e2 < 14) {
                int nsA = __shfl_sync(0xffffffffu, mySrc, hb + e2 + 2);
                int nsB = __shfl_sync(0xffffffffu, mySrc, hb + e2 + 3);
                nkA = *(float4*)&g_k[nsA * 64 + c0];
                nkB = *(float4*)&g_k[nsB * 64 + c0];
            }
            float rA0 = __shfl_sync(0xffffffffu, r0, hb + e2);
            float rA1 = __shfl_sync(0xffffffffu, r1, hb + e2);
            float rA2 = __shfl_sync(0xffffffffu, r2, hb + e2);
            float rB0 = __shfl_sync(0xffffffffu, r0, hb + e2 + 1);
            float rB1 = __shfl_sync(0xffffffffu, r1, hb + e2 + 1);
            float rB2 = __shfl_sync(0xffffffffu, r2, hb + e2 + 1);
            float kvA[4] = {kA.x, kA.y, kA.z, kA.w};
            float kvB[4] = {kB.x, kB.y, kB.z, kB.w};
            float pa[4], pbv[4];
            #pragma unroll
            for (int i = 0; i < 4; i++) {
                float dlA = fmaf(rA0, pw0[i], fmaf(rA1, pw1[i], fmaf(rA2, pw2[i], pb[i])));
                float a0A = kvA[i] - qv[i] + dlA;
                pa[i] = fmaxf(fmaf(a0A, scA[i], shA[i]), 0.f);
                float dlB = fmaf(rB0, pw0[i], fmaf(rB1, pw1[i], fmaf(rB2, pw2[i], pb[i])));
                float a0B = kvB[i] - qv[i] + dlB;
                pbv[i] = fmaxf(fmaf(a0B, scA[i], shA[i]), 0.f);
            }
            float accA[8], accB[8];
            #pragma unroll
            for (int s = 0; s < 8; s++) {
                accA[s] = fmaf(pa[0], rW[s][0], fmaf(pa[1], rW[s][1],
                          fmaf(pa[2], rW[s][2], pa[3] * rW[s][3])));
                accB[s] = fmaf(pbv[0], rW[s][0], fmaf(pbv[1], rW[s][1],
                          fmaf(pbv[2], rW[s][2], pbv[3] * rW[s][3])));
            }
            #pragma unroll
            for (int s = 0; s < 8; s++) {
                accA[s] += __shfl_xor_sync(0xffffffffu, accA[s], 8);
                accB[s] += __shfl_xor_sync(0xffffffffu, accB[s], 8);
            }
            bool hb3 = (lane & 8) != 0;
            float c4A[4], c4B[4];
            #pragma unroll
            for (int i = 0; i < 4; i++) {
                c4A[i] = hb3 ? accA[4 + i] : accA[i];
                c4B[i] = hb3 ? accB[4 + i] : accB[i];
            }
            #pragma unroll
            for (int i = 0; i < 4; i++) {
                c4A[i] += __shfl_xor_sync(0xffffffffu, c4A[i], 4);
                c4B[i] += __shfl_xor_sync(0xffffffffu, c4B[i], 4);
            }
            bool hb2 = (lane & 4) != 0;
            float c2aA = hb2 ? c4A[2] : c4A[0];
            float c2bA = hb2 ? c4A[3] : c4A[1];
            float c2aB = hb2 ? c4B[2] : c4B[0];
            float c2bB = hb2 ? c4B[3] : c4B[1];
            c2aA += __shfl_xor_sync(0xffffffffu, c2aA, 2);
            c2bA += __shfl_xor_sync(0xffffffffu, c2bA, 2);
            c2aB += __shfl_xor_sync(0xffffffffu, c2aB, 2);
            c2bB += __shfl_xor_sync(0xffffffffu, c2bB, 2);
            bool hb1 = (lane & 2) != 0;
            float c1A = hb1 ? c2bA : c2aA;
            float c1B = hb1 ? c2bB : c2aB;
            c1A += __shfl_xor_sync(0xffffffffu, c1A, 1);
            c1B += __shfl_xor_sync(0xffffffffu, c1B, 1);
            if ((lane & 1) == 0) {
                float fA = c1A + w1bl;
                float fB = c1B + w1bl;
                g_a1[(ebase + e2) * 8 + s_mine] = fA;
                g_a1[(ebase + e2 + 1) * 8 + s_mine] = fB;
                ls += fA + fB;
                lq = fmaf(fA, fA, lq);
                lq = fmaf(fB, fB, lq);
            }
            kA = nkA; kB = nkB;
        }
    }
    if ((lane & 1) == 0) {
        atomicAdd(&ssum[s_mine], ls);
        atomicAdd(&ssq[s_mine], lq);
    }
    __syncthreads();
    if (tid < 8) {
        atomicAdd(&g_st[ST_W2 + tid], (double)ssum[tid]);
        atomicAdd(&g_st[ST_W2 + 8 + tid], (double)ssq[tid]);
    }
}

// ---------------- aggregate: a2 + softmax + weighted sum; bn2 stats ------
__global__ void __launch_bounds__(256) k_aggr(const float* __restrict__ pbg,
                                              const float* __restrict__ pbb,
                                              const float* __restrict__ p2w,
                                              const float* __restrict__ p2b,
                                              const float* __restrict__ wb2g,
                                              const float* __restrict__ wb2b,
                                              const float* __restrict__ w2w,
                                              const float* __restrict__ w2b) {
    __shared__ float sAttn[8][2][16][8];
    __shared__ float sR[8][2][16][3];
    __shared__ int   sSrc[8][2][16];
    __shared__ float sRagg[8][2][8][3];
    __shared__ float sp2[64][4];
    __shared__ float sw2[64];
    __shared__ float sw2b[8];
    __shared__ float ssum[64], ssq[64];
    __shared__ float s_tsc[3], s_tsh[3], s_sc2[8], s_sh2[8];

    int tid = threadIdx.x;
    int warp = tid >> 5, lane = tid & 31;
    {
        int c = tid >> 2, j = tid & 3;
        sp2[c][j] = (j < 3) ? p2w[c * 3 + j] : p2b[c];
    }
    if (tid < 64) { sw2[tid] = w2w[tid]; ssum[tid] = 0.f; ssq[tid] = 0.f; }
    if (tid >= 64 && tid < 72) sw2b[tid - 64] = w2b[tid - 64];
    if (tid >= 72 && tid < 75)
        bn_coef(ST_T, 3, tid - 72, INV_E, pbg, pbb, s_tsc[tid - 72], s_tsh[tid - 72]);
    if (tid >= 80 && tid < 88)
        bn_coef(ST_W2, 8, tid - 80, INV_E, wb2g, wb2b, s_sc2[tid - 80], s_sh2[tid - 80]);
    __syncthreads();

    int nodeBase = blockIdx.x * 16 + warp * 2;
    int sub = lane >> 4, el = lane & 15;
    int node = nodeBase + sub;
    int e = node * 16 + el;
    int src = g_src[e];
    sSrc[warp][sub][el] = src;
    float4 t = g_t4[e];
    float r0 = fmaxf(fmaf(t.x, s_tsc[0], s_tsh[0]), 0.f);
    float r1 = fmaxf(fmaf(t.y, s_tsc[1], s_tsh[1]), 0.f);
    float r2 = fmaxf(fmaf(t.z, s_tsc[2], s_tsh[2]), 0.f);
    sR[warp][sub][el][0] = r0; sR[warp][sub][el][1] = r1; sR[warp][sub][el][2] = r2;

    float4 a1lo = *(float4*)&g_a1[e * 8];
    float4 a1hi = *(float4*)&g_a1[e * 8 + 4];
    float av[8] = {a1lo.x, a1lo.y, a1lo.z, a1lo.w, a1hi.x, a1hi.y, a1hi.z, a1hi.w};
    float pbn[8];
    #pragma unroll
    for (int s = 0; s < 8; s++)
        pbn[s] = fmaxf(fmaf(av[s], s_sc2[s], s_sh2[s]), 0.f);
    #pragma unroll
    for (int s = 0; s < 8; s++) {
        float a2 = sw2b[s];
        #pragma unroll
        for (int s2 = 0; s2 < 8; s2++) a2 = fmaf(pbn[s2], sw2[s * 8 + s2], a2);
        float mx = a2;
        #pragma unroll
        for (int m = 8; m; m >>= 1) mx = fmaxf(mx, __shfl_xor_sync(0xffffffffu, mx, m));
        float ex = __expf(a2 - mx);
        float sm = ex;
        #pragma unroll
        for (int m = 8; m; m >>= 1) sm += __shfl_xor_sync(0xffffffffu, sm, m);
        sAttn[warp][sub][el][s] = ex / sm;
    }
    __syncwarp();

    if (lane < 24) {
        int g = lane / 3, comp = lane % 3;
        #pragma unroll
        for (int sb = 0; sb < 2; sb++) {
            float rag = 0.f;
            #pragma unroll
            for (int e2 = 0; e2 < 16; e2++)
                rag = fmaf(sAttn[warp][sb][e2][g], sR[warp][sb][e2][comp], rag);
            sRagg[warp][sb][g][comp] = rag;
        }
    }
    __syncwarp();

    int gl = lane & 7;
    int c0 = lane, c1 = lane + 32;
    #pragma unroll
    for (int sb = 0; sb < 2; sb++) {
        int nd = nodeBase + sb;
        float rag0 = sRagg[warp][sb][gl][0];
        float rag1 = sRagg[warp][sb][gl][1];
        float rag2 = sRagg[warp][sb][gl][2];
        float acc0 = fmaf(sp2[c0][0], rag0, fmaf(sp2[c0][1], rag1,
                     fmaf(sp2[c0][2], rag2, sp2[c0][3])));
        float acc1 = fmaf(sp2[c1][0], rag0, fmaf(sp2[c1][1], rag1,
                     fmaf(sp2[c1][2], rag2, sp2[c1][3])));
        #pragma unroll
        for (int e2 = 0; e2 < 16; e2++) {
            float at = sAttn[warp][sb][e2][gl];
            const float* vr = &g_v[sSrc[warp][sb][e2] * 64];
            acc0 = fmaf(at, vr[c0], acc0);
            acc1 = fmaf(at, vr[c1], acc1);
        }
        g_out[nd * 64 + c0] = acc0;
        g_out[nd * 64 + c1] = acc1;
        atomicAdd(&ssum[c0], acc0); atomicAdd(&ssq[c0], acc0 * acc0);
        atomicAdd(&ssum[c1], acc1); atomicAdd(&ssq[c1], acc1 * acc1);
    }
    __syncthreads();
    if (tid < 64) {
        atomicAdd(&g_st[ST_BN2 + tid], (double)ssum[tid]);
        atomicAdd(&g_st[ST_BN2 + 64 + tid], (double)ssq[tid]);
    }
}

// ---------------- GEMM 3: y3 = relu(bn2(out)) @ W3^T; bn3 stats ----------
__global__ void __launch_bounds__(256) k_lin3(const float* __restrict__ g2,
                                              const float* __restrict__ b2) {
    extern __shared__ float dyn[];
    float* sWT = dyn;
    float* sX  = dyn + 4096;
    __shared__ float ssc[64], ssh[64];
    __shared__ float ssum[64], ssq[64];
    int tid = threadIdx.x;
    #pragma unroll
    for (int i = tid; i < 4096; i += 256) sWT[i] = g_WT[4][i];
    if (tid < 64) {
        bn_coef(ST_BN2, 64, tid, INV_N, g2, b2, ssc[tid], ssh[tid]);
        ssum[tid] = 0.f; ssq[tid] = 0.f;
    }
    __syncthreads();
    int base = blockIdx.x * 128;
    #pragma unroll
    for (int i = tid; i < 8192; i += 256) {
        int n = i >> 6, c = i & 63;
        float y = g_out[(base + n) * 64 + c];
        sX[n * 68 + c] = fmaxf(fmaf(y, ssc[c], ssh[c]), 0.f);
    }
    __syncthreads();
    int o0 = (tid & 15) * 4;
    int n0 = (tid >> 4) * 8;
    float acc[8][4];
    #pragma unroll
    for (int i = 0; i < 8; i++)
        #pragma unroll
        for (int c = 0; c < 4; c++) acc[i][c] = 0.f;
    #pragma unroll
    for (int j = 0; j < 64; j += 4) {
        float4 xv[8];
        #pragma unroll
        for (int i = 0; i < 8; i++) xv[i] = *(float4*)(sX + (n0 + i) * 68 + j);
        #pragma unroll
        for (int jj = 0; jj < 4; jj++) {
            float4 wv = *(float4*)(sWT + (j + jj) * 64 + o0);
            #pragma unroll
            for (int i = 0; i < 8; i++) {
                float h = ((const float*)&xv[i])[jj];
                acc[i][0] = fmaf(h, wv.x, acc[i][0]);
                acc[i][1] = fmaf(h, wv.y, acc[i][1]);
                acc[i][2] = fmaf(h, wv.z, acc[i][2]);
                acc[i][3] = fmaf(h, wv.w, acc[i][3]);
            }
        }
    }
    float ts[4] = {0, 0, 0, 0}, tq[4] = {0, 0, 0, 0};
    #pragma unroll
    for (int i = 0; i < 8; i++) {
        *(float4*)&g_y3[(base + n0 + i) * 64 + o0] =
            make_float4(acc[i][0], acc[i][1], acc[i][2], acc[i][3]);
        #pragma unroll
        for (int c = 0; c < 4; c++) { ts[c] += acc[i][c]; tq[c] = fmaf(acc[i][c], acc[i][c], tq[c]); }
    }
    #pragma unroll
    for (int c = 0; c < 4; c++) {
        atomicAdd(&ssum[o0 + c], ts[c]);
        atomicAdd(&ssq[o0 + c], tq[c]);
    }
    __syncthreads();
    if (tid < 64) {
        atomicAdd(&g_st[ST_BN3 + tid], (double)ssum[tid]);
        atomicAdd(&g_st[ST_BN3 + 64 + tid], (double)ssq[tid]);
    }
}

// ---------------- final: relu(bn3(y3) + x) --------------------------------
__global__ void __launch_bounds__(256) k_final(const float* __restrict__ x,
                                               const float* __restrict__ g3,
                                               const float* __restrict__ b3,
                                               float* __restrict__ out) {
    __shared__ float ssc[64], ssh[64];
    int tid = threadIdx.x;
    if (tid < 64) bn_coef(ST_BN3, 64, tid, INV_N, g3, b3, ssc[tid], ssh[tid]);
    __syncthreads();
    int gid = blockIdx.x * 256 + tid;
    int i = gid * 4;
    int c0 = i & 63;
    float4 y = *(float4*)&g_y3[i];
    float4 xv = *(const float4*)&x[i];
    float4 r;
    r.x = fmaxf(fmaf(y.x, ssc[c0 + 0], ssh[c0 + 0]) + xv.x, 0.f);
    r.y = fmaxf(fmaf(y.y, ssc[c0 + 1], ssh[c0 + 1]) + xv.y, 0.f);
    r.z = fmaxf(fmaf(y.z, ssc[c0 + 2], ssh[c0 + 2]) + xv.z, 0.f);
    r.w = fmaxf(fmaf(y.w, ssc[c0 + 3], ssh[c0 + 3]) + xv.w, 0.f);
    *(float4*)&out[i] = r;
}

// ---------------- launch ---------------------------------------------------
extern "C" void kernel_launch(void* const* d_in, const int* in_sizes, int n_in,
                              void* d_out, int out_size) {
    const float* pos  = (const float*)d_in[0];
    const float* x    = (const float*)d_in[1];
    const float* W1   = (const float*)d_in[2];
    const float* Wk   = (const float*)d_in[3];
    const float* bk   = (const float*)d_in[4];
    const float* Wq   = (const float*)d_in[5];
    const float* bq   = (const float*)d_in[6];
    const float* Wv   = (const float*)d_in[7];
    const float* bv   = (const float*)d_in[8];
    const float* p1w  = (const float*)d_in[9];
    const float* p1b  = (const float*)d_in[10];
    const float* pbg  = (const float*)d_in[11];
    const float* pbb  = (const float*)d_in[12];
    const float* p2w  = (const float*)d_in[13];
    const float* p2b  = (const float*)d_in[14];
    const float* wb1g = (const float*)d_in[15];
    const float* wb1b = (const float*)d_in[16];
    const float* w1w  = (const float*)d_in[17];
    const float* w1b  = (const float*)d_in[18];
    const float* wb2g = (const float*)d_in[19];
    const float* wb2b = (const float*)d_in[20];
    const float* w2w  = (const float*)d_in[21];
    const float* w2b  = (const float*)d_in[22];
    const float* W3   = (const float*)d_in[23];
    const float* g1   = (const float*)d_in[24];
    const float* b1   = (const float*)d_in[25];
    const float* g2   = (const float*)d_in[26];
    const float* b2   = (const float*)d_in[27];
    const float* g3   = (const float*)d_in[28];
    const float* b3   = (const float*)d_in[29];
    const int*   ei   = (const int*)d_in[30];
    float* out = (float*)d_out;

    cudaFuncSetAttribute(k_early, cudaFuncAttributeMaxDynamicSharedMemorySize, GEMM_SMEM);
    cudaFuncSetAttribute(k_lin3,  cudaFuncAttributeMaxDynamicSharedMemorySize, GEMM_SMEM);
    cudaFuncSetAttribute(k_kq,    cudaFuncAttributeMaxDynamicSharedMemorySize, GEMM_SMEM);
    cudaFuncSetAttribute(k_a0v,   cudaFuncAttributeMaxDynamicSharedMemorySize, GEMM_SMEM);

    k_prep<<<80, 256>>>(W1, Wk, Wq, Wv, W3);
    k_early<<<256 + EE / 256, 256, GEMM_SMEM>>>(x, ei, pos, p1w, p1b);
    k_kq<<<NN / 128, 256, GEMM_SMEM>>>(bk, bq, g1, b1);
    k_a0v<<<256 + A0_EDGE_BLOCKS, 256, GEMM_SMEM>>>(bv, g1, b1, pbg, pbb, p2w, p2b);
    k_a1<<<1184, 256>>>(pbg, pbb, p2w, p2b, wb1g, wb1b, w1w, w1b);
    k_aggr<<<NN / 16, 256>>>(pbg, pbb, p2w, p2b, wb2g, wb2b, w2w, w2b);
    k_lin3<<<NN / 128, 256, GEMM_SMEM>>>(g2, b2);
    k_final<<<(NN * CC) / 1024, 256>>>(x, g3, b3, out);
}

// round 16
// speedup vs baseline: 1.1711x; 1.0958x over previous
#include <cuda_runtime.h>

#define NN 32768
#define CC 64
#define KK 16
#define SS 8
#define EE (NN * KK)
#define EPS 1e-5f

// ---------------- scratch ----------------
__device__ float g_y1[NN * CC];
__device__ float g_k[NN * CC];
__device__ float g_q[NN * CC];
__device__ float g_v[NN * CC];
__device__ float g_a1[EE * SS];
__device__ float g_out[NN * CC];
__device__ float g_y3[NN * CC];
__device__ int   g_src[EE];
__device__ float4 g_t4[EE];
__device__ float g_WT[5][4096];   // [j*64+o]; 0=W1,1=Wk,2=Wq,3=Wv,4=W3

#define ST_BN1 0
#define ST_T   128
#define ST_W1  134
#define ST_W2  262
#define ST_BN2 278
#define ST_BN3 406
#define ST_TOT 534
__device__ double g_st[ST_TOT];

#define INV_N  (1.0 / (double)NN)
#define INV_E  (1.0 / (double)EE)

// dynamic smem: weights (4096) + X tile (128*68)
#define GEMM_SMEM ((4096 + 128 * 68) * 4)
#define A0_EDGE_BLOCKS 1072
#define A1_BLOCKS 888
#define AGGR_BLOCKS 592

__device__ __forceinline__ void bn_coef(int off, int nch, int c, double inv_cnt,
                                        const float* __restrict__ g,
                                        const float* __restrict__ b,
                                        float& scale, float& shift) {
    double m = g_st[off + c] * inv_cnt;
    double v = g_st[off + nch + c] * inv_cnt - m * m;
    float rs = rsqrtf(fmaxf((float)v, 0.f) + EPS);
    scale = rs * __ldg(&g[c]);
    shift = __ldg(&b[c]) - (float)m * scale;
}

// shared GEMM body: 128-node tile, 8 nodes x 4 outputs per thread
__device__ __forceinline__ void gemm_tile(const float* sWT, const float* sX,
                                          float* dstBase, int base, int tid,
                                          float bo0, float bo1, float bo2, float bo3) {
    int o0 = (tid & 15) * 4;
    int n0 = (tid >> 4) * 8;
    float acc[8][4];
    #pragma unroll
    for (int i = 0; i < 8; i++)
        #pragma unroll
        for (int c = 0; c < 4; c++) acc[i][c] = 0.f;
    #pragma unroll
    for (int j = 0; j < 64; j += 4) {
        float4 xv[8];
        #pragma unroll
        for (int i = 0; i < 8; i++) xv[i] = *(float4*)(sX + (n0 + i) * 68 + j);
        #pragma unroll
        for (int jj = 0; jj < 4; jj++) {
            float4 wv = *(float4*)(sWT + (j + jj) * 64 + o0);
            #pragma unroll
            for (int i = 0; i < 8; i++) {
                float h = ((const float*)&xv[i])[jj];
                acc[i][0] = fmaf(h, wv.x, acc[i][0]);
                acc[i][1] = fmaf(h, wv.y, acc[i][1]);
                acc[i][2] = fmaf(h, wv.z, acc[i][2]);
                acc[i][3] = fmaf(h, wv.w, acc[i][3]);
            }
        }
    }
    #pragma unroll
    for (int i = 0; i < 8; i++)
        *(float4*)&dstBase[(base + n0 + i) * 64 + o0] =
            make_float4(acc[i][0] + bo0, acc[i][1] + bo1, acc[i][2] + bo2, acc[i][3] + bo3);
}

// ---------------- prep: zero stats + transpose weights -------------------
__global__ void k_prep(const float* __restrict__ W1, const float* __restrict__ Wk,
                       const float* __restrict__ Wq, const float* __restrict__ Wv,
                       const float* __restrict__ W3) {
    int i = blockIdx.x * 256 + threadIdx.x;
    if (i < ST_TOT) g_st[i] = 0.0;
    if (i < 5 * 4096) {
        int m = i >> 12, r = i & 4095;
        int o = r >> 6, j = r & 63;
        const float* W = (m == 0) ? W1 : (m == 1) ? Wk : (m == 2) ? Wq : (m == 3) ? Wv : W3;
        g_WT[m][j * 64 + o] = W[o * 64 + j];
    }
}

// ---------------- early: lin1 (blocks 0..255) + cvt/t-stats (256..2303) ---
__global__ void __launch_bounds__(256) k_early(const float* __restrict__ x,
                                               const int* __restrict__ ei32,
                                               const float* __restrict__ pos,
                                               const float* __restrict__ p1w,
                                               const float* __restrict__ p1b) {
    int tid = threadIdx.x;
    if (blockIdx.x < 256) {
        extern __shared__ float dyn[];
        float* sWT = dyn;
        float* sX  = dyn + 4096;
        __shared__ float ssum[64], ssq[64];
        #pragma unroll
        for (int i = tid; i < 4096; i += 256) sWT[i] = g_WT[0][i];
        if (tid < 64) { ssum[tid] = 0.f; ssq[tid] = 0.f; }
        int base = blockIdx.x * 128;
        #pragma unroll
        for (int i = tid; i < 8192; i += 256) {
            int n = i >> 6, c = i & 63;
            sX[n * 68 + c] = x[(base + n) * 64 + c];
        }
        __syncthreads();
        int o0 = (tid & 15) * 4;
        int n0 = (tid >> 4) * 8;
        float acc[8][4];
        #pragma unroll
        for (int i = 0; i < 8; i++)
            #pragma unroll
            for (int c = 0; c < 4; c++) acc[i][c] = 0.f;
        #pragma unroll
        for (int j = 0; j < 64; j += 4) {
            float4 xv[8];
            #pragma unroll
            for (int i = 0; i < 8; i++) xv[i] = *(float4*)(sX + (n0 + i) * 68 + j);
            #pragma unroll
            for (int jj = 0; jj < 4; jj++) {
                float4 wv = *(float4*)(sWT + (j + jj) * 64 + o0);
                #pragma unroll
                for (int i = 0; i < 8; i++) {
                    float h = ((const float*)&xv[i])[jj];
                    acc[i][0] = fmaf(h, wv.x, acc[i][0]);
                    acc[i][1] = fmaf(h, wv.y, acc[i][1]);
                    acc[i][2] = fmaf(h, wv.z, acc[i][2]);
                    acc[i][3] = fmaf(h, wv.w, acc[i][3]);
                }
            }
        }
        float ts[4] = {0, 0, 0, 0}, tq[4] = {0, 0, 0, 0};
        #pragma unroll
        for (int i = 0; i < 8; i++) {
            *(float4*)&g_y1[(base + n0 + i) * 64 + o0] =
                make_float4(acc[i][0], acc[i][1], acc[i][2], acc[i][3]);
            #pragma unroll
            for (int c = 0; c < 4; c++) { ts[c] += acc[i][c]; tq[c] = fmaf(acc[i][c], acc[i][c], tq[c]); }
        }
        #pragma unroll
        for (int c = 0; c < 4; c++) {
            atomicAdd(&ssum[o0 + c], ts[c]);
            atomicAdd(&ssq[o0 + c], tq[c]);
        }
        __syncthreads();
        if (tid < 64) {
            atomicAdd(&g_st[ST_BN1 + tid], (double)ssum[tid]);
            atomicAdd(&g_st[ST_BN1 + 64 + tid], (double)ssq[tid]);
        }
    } else {
        __shared__ float red[6];
        if (tid < 6) red[tid] = 0.f;
        bool is32 = (ei32[EE + 16] == 1) && (ei32[EE + 17] == 1) && (ei32[EE + 31] == 1);
        float w[9], b3[3];
        #pragma unroll
        for (int i = 0; i < 9; i++) w[i] = __ldg(&p1w[i]);
        #pragma unroll
        for (int i = 0; i < 3; i++) b3[i] = __ldg(&p1b[i]);
        __syncthreads();
        int e = (blockIdx.x - 256) * 256 + tid;
        int src = is32 ? ei32[e] : ei32[2 * e];
        g_src[e] = src;
        int d = e >> 4;
        float rx = pos[src * 3 + 0] - pos[d * 3 + 0];
        float ry = pos[src * 3 + 1] - pos[d * 3 + 1];
        float rz = pos[src * 3 + 2] - pos[d * 3 + 2];
        float t0 = fmaf(w[0], rx, fmaf(w[1], ry, fmaf(w[2], rz, b3[0])));
        float t1 = fmaf(w[3], rx, fmaf(w[4], ry, fmaf(w[5], rz, b3[1])));
        float t2 = fmaf(w[6], rx, fmaf(w[7], ry, fmaf(w[8], rz, b3[2])));
        g_t4[e] = make_float4(t0, t1, t2, 0.f);
        float s0 = t0, s1 = t1, s2 = t2, q0 = t0 * t0, q1 = t1 * t1, q2 = t2 * t2;
        #pragma unroll
        for (int m = 16; m; m >>= 1) {
            s0 += __shfl_xor_sync(0xffffffffu, s0, m);
            s1 += __shfl_xor_sync(0xffffffffu, s1, m);
            s2 += __shfl_xor_sync(0xffffffffu, s2, m);
            q0 += __shfl_xor_sync(0xffffffffu, q0, m);
            q1 += __shfl_xor_sync(0xffffffffu, q1, m);
            q2 += __shfl_xor_sync(0xffffffffu, q2, m);
        }
        if ((tid & 31) == 0) {
            atomicAdd(&red[0], s0); atomicAdd(&red[1], s1); atomicAdd(&red[2], s2);
            atomicAdd(&red[3], q0); atomicAdd(&red[4], q1); atomicAdd(&red[5], q2);
        }
        __syncthreads();
        if (tid < 6) atomicAdd(&g_st[ST_T + tid], (double)red[tid]);
    }
}

// ---------------- kq fused: one sX fill, weight reload between passes ----
__global__ void __launch_bounds__(256) k_kq(const float* __restrict__ bk,
                                            const float* __restrict__ bq,
                                            const float* __restrict__ g1,
                                            const float* __restrict__ b1) {
    extern __shared__ float dyn[];
    float* sWT = dyn;
    float* sX  = dyn + 4096;
    __shared__ float ssc[64], ssh[64];
    int tid = threadIdx.x;
    #pragma unroll
    for (int i = tid; i < 4096; i += 256) sWT[i] = g_WT[1][i];
    if (tid < 64) bn_coef(ST_BN1, 64, tid, INV_N, g1, b1, ssc[tid], ssh[tid]);
    __syncthreads();
    int base = blockIdx.x * 128;
    #pragma unroll
    for (int i = tid; i < 8192; i += 256) {
        int n = i >> 6, c = i & 63;
        float y = g_y1[(base + n) * 64 + c];
        sX[n * 68 + c] = fmaxf(fmaf(y, ssc[c], ssh[c]), 0.f);
    }
    __syncthreads();
    int o0 = (tid & 15) * 4;
    for (int m = 0; m < 2; m++) {
        const float* bias = (m == 0) ? bk : bq;
        float* dst = (m == 0) ? g_k : g_q;
        float bo0 = __ldg(&bias[o0]), bo1 = __ldg(&bias[o0 + 1]),
              bo2 = __ldg(&bias[o0 + 2]), bo3 = __ldg(&bias[o0 + 3]);
        gemm_tile(sWT, sX, dst, base, tid, bo0, bo1, bo2, bo3);
        if (m == 0) {
            __syncthreads();
            #pragma unroll
            for (int i = tid; i < 4096; i += 256) sWT[i] = g_WT[2][i];
            __syncthreads();
        }
    }
}

// ---------------- a0 stats (blocks 256+) co-scheduled with v GEMM (0..255)
__global__ void __launch_bounds__(256) k_a0v(const float* __restrict__ bv,
                                             const float* __restrict__ g1,
                                             const float* __restrict__ b1,
                                             const float* __restrict__ pbg,
                                             const float* __restrict__ pbb,
                                             const float* __restrict__ p2w,
                                             const float* __restrict__ p2b) {
    int tid = threadIdx.x;
    if (blockIdx.x < 256) {
        // ===== v = relu(bn1(y1)) @ Wv^T + bv =====
        extern __shared__ float dyn[];
        float* sWT = dyn;
        float* sX  = dyn + 4096;
        __shared__ float ssc[64], ssh[64];
        #pragma unroll
        for (int i = tid; i < 4096; i += 256) sWT[i] = g_WT[3][i];
        if (tid < 64) bn_coef(ST_BN1, 64, tid, INV_N, g1, b1, ssc[tid], ssh[tid]);
        __syncthreads();
        int base = blockIdx.x * 128;
        #pragma unroll
        for (int i = tid; i < 8192; i += 256) {
            int n = i >> 6, c = i & 63;
            float y = g_y1[(base + n) * 64 + c];
            sX[n * 68 + c] = fmaxf(fmaf(y, ssc[c], ssh[c]), 0.f);
        }
        __syncthreads();
        int o0 = (tid & 15) * 4;
        float bo0 = __ldg(&bv[o0]), bo1 = __ldg(&bv[o0 + 1]),
              bo2 = __ldg(&bv[o0 + 2]), bo3 = __ldg(&bv[o0 + 3]);
        gemm_tile(sWT, sX, g_v, base, tid, bo0, bo1, bo2, bo3);
        return;
    }
    // ===== a0 stats: node-blocked, 4-edge batch, late rr-shuffles =====
    __shared__ float ssum[64], ssq[64];
    __shared__ float s_tsc[3], s_tsh[3];
    if (tid < 64) { ssum[tid] = 0.f; ssq[tid] = 0.f; }
    if (tid >= 64 && tid < 67)
        bn_coef(ST_T, 3, tid - 64, INV_E, pbg, pbb, s_tsc[tid - 64], s_tsh[tid - 64]);
    int lane = tid & 31;
    int half = lane >> 4;
    int el = lane & 15;
    int c0 = el * 4;
    int hb = half << 4;
    float pw0[4], pw1[4], pw2[4], pb[4];
    #pragma unroll
    for (int i = 0; i < 4; i++) {
        pw0[i] = __ldg(&p2w[(c0 + i) * 3 + 0]);
        pw1[i] = __ldg(&p2w[(c0 + i) * 3 + 1]);
        pw2[i] = __ldg(&p2w[(c0 + i) * 3 + 2]);
        pb[i]  = __ldg(&p2b[c0 + i]);
    }
    float sums[4] = {0, 0, 0, 0}, sqs[4] = {0, 0, 0, 0};
    __syncthreads();
    float tsc[3], tsh[3];
    #pragma unroll
    for (int i = 0; i < 3; i++) { tsc[i] = s_tsc[i]; tsh[i] = s_tsh[i]; }
    int gw = ((blockIdx.x - 256) * 256 + tid) >> 5;
    int nw = ((gridDim.x - 256) * 256) >> 5;
    for (int np = gw; np < NN / 2; np += nw) {
        int node = 2 * np + half;
        int ebase = node * 16;
        int mySrc = g_src[ebase + el];
        float4 t = g_t4[ebase + el];
        float r0 = fmaxf(fmaf(t.x, tsc[0], tsh[0]), 0.f);
        float r1 = fmaxf(fmaf(t.y, tsc[1], tsh[1]), 0.f);
        float r2 = fmaxf(fmaf(t.z, tsc[2], tsh[2]), 0.f);
        float4 q4 = *(float4*)&g_q[node * 64 + c0];
        float qv[4] = {q4.x, q4.y, q4.z, q4.w};
        #pragma unroll
        for (int e2 = 0; e2 < 16; e2 += 4) {
            int s[4];
            #pragma unroll
            for (int j = 0; j < 4; j++)
                s[j] = __shfl_sync(0xffffffffu, mySrc, hb + e2 + j);
            float4 kk[4];
            #pragma unroll
            for (int j = 0; j < 4; j++) kk[j] = *(float4*)&g_k[s[j] * 64 + c0];
            #pragma unroll
            for (int j = 0; j < 4; j++) {
                float rr0 = __shfl_sync(0xffffffffu, r0, hb + e2 + j);
                float rr1 = __shfl_sync(0xffffffffu, r1, hb + e2 + j);
                float rr2 = __shfl_sync(0xffffffffu, r2, hb + e2 + j);
                float kv[4] = {kk[j].x, kk[j].y, kk[j].z, kk[j].w};
                #pragma unroll
                for (int i = 0; i < 4; i++) {
                    float dl = fmaf(rr0, pw0[i], fmaf(rr1, pw1[i],
                               fmaf(rr2, pw2[i], pb[i])));
                    float a0 = kv[i] - qv[i] + dl;
                    sums[i] += a0;
                    sqs[i] = fmaf(a0, a0, sqs[i]);
                }
            }
        }
    }
    #pragma unroll
    for (int i = 0; i < 4; i++) {
        atomicAdd(&ssum[c0 + i], sums[i]);
        atomicAdd(&ssq[c0 + i], sqs[i]);
    }
    __syncthreads();
    if (tid < 64) {
        atomicAdd(&g_st[ST_W1 + tid], (double)ssum[tid]);
        atomicAdd(&g_st[ST_W1 + 64 + tid], (double)ssq[tid]);
    }
}

// ---------------- a1: node-blocked; prefetched gathers, paired trees -----
__global__ void __launch_bounds__(256) k_a1(const float* __restrict__ pbg,
                                            const float* __restrict__ pbb,
                                            const float* __restrict__ p2w,
                                            const float* __restrict__ p2b,
                                            const float* __restrict__ wb1g,
                                            const float* __restrict__ wb1b,
                                            const float* __restrict__ w1w,
                                            const float* __restrict__ w1b) {
    __shared__ float ssum[8], ssq[8];
    __shared__ float s_tsc[3], s_tsh[3];
    __shared__ float s_scA[64], s_shA[64];
    int tid = threadIdx.x;
    if (tid < 8) { ssum[tid] = 0.f; ssq[tid] = 0.f; }
    if (tid >= 64 && tid < 67)
        bn_coef(ST_T, 3, tid - 64, INV_E, pbg, pbb, s_tsc[tid - 64], s_tsh[tid - 64]);
    if (tid < 64)
        bn_coef(ST_W1, 64, tid, INV_E, wb1g, wb1b, s_scA[tid], s_shA[tid]);
    int lane = tid & 31;
    int half = lane >> 4;
    int el = lane & 15;
    int c0 = el * 4;
    int hb = half << 4;
    float pw0[4], pw1[4], pw2[4], pb[4];
    #pragma unroll
    for (int i = 0; i < 4; i++) {
        pw0[i] = __ldg(&p2w[(c0 + i) * 3 + 0]);
        pw1[i] = __ldg(&p2w[(c0 + i) * 3 + 1]);
        pw2[i] = __ldg(&p2w[(c0 + i) * 3 + 2]);
        pb[i]  = __ldg(&p2b[c0 + i]);
    }
    float rW[8][4];
    #pragma unroll
    for (int s = 0; s < 8; s++)
        #pragma unroll
        for (int i = 0; i < 4; i++)
            rW[s][i] = __ldg(&w1w[s * 64 + c0 + i]);
    int s_mine = (lane >> 1) & 7;
    float w1bl = __ldg(&w1b[s_mine]);
    float ls = 0.f, lq = 0.f;
    __syncthreads();
    float tsc[3], tsh[3], scA[4], shA[4];
    #pragma unroll
    for (int i = 0; i < 3; i++) { tsc[i] = s_tsc[i]; tsh[i] = s_tsh[i]; }
    #pragma unroll
    for (int i = 0; i < 4; i++) { scA[i] = s_scA[c0 + i]; shA[i] = s_shA[c0 + i]; }
    int gw = (blockIdx.x * 256 + tid) >> 5;
    int nw = (gridDim.x * 256) >> 5;
    for (int np = gw; np < NN / 2; np += nw) {
        int node = 2 * np + half;
        int ebase = node * 16;
        int mySrc = g_src[ebase + el];
        float4 t = g_t4[ebase + el];
        float r0 = fmaxf(fmaf(t.x, tsc[0], tsh[0]), 0.f);
        float r1 = fmaxf(fmaf(t.y, tsc[1], tsh[1]), 0.f);
        float r2 = fmaxf(fmaf(t.z, tsc[2], tsh[2]), 0.f);
        float4 q4 = *(float4*)&g_q[node * 64 + c0];
        float qv[4] = {q4.x, q4.y, q4.z, q4.w};
        // prefetch first pair
        int srcA = __shfl_sync(0xffffffffu, mySrc, hb + 0);
        int srcB = __shfl_sync(0xffffffffu, mySrc, hb + 1);
        float4 kA = *(float4*)&g_k[srcA * 64 + c0];
        float4 kB = *(float4*)&g_k[srcB * 64 + c0];
        #pragma unroll
        for (int e2 = 0; e2 < 16; e2 += 2) {
            float4 nkA, nkB;
            if (e2 < 14) {
                int nsA = __shfl_sync(0xffffffffu, mySrc, hb + e2 + 2);
                int nsB = __shfl_sync(0xffffffffu, mySrc, hb + e2 + 3);
                nkA = *(float4*)&g_k[nsA * 64 + c0];
                nkB = *(float4*)&g_k[nsB * 64 + c0];
            }
            float rA0 = __shfl_sync(0xffffffffu, r0, hb + e2);
            float rA1 = __shfl_sync(0xffffffffu, r1, hb + e2);
            float rA2 = __shfl_sync(0xffffffffu, r2, hb + e2);
            float rB0 = __shfl_sync(0xffffffffu, r0, hb + e2 + 1);
            float rB1 = __shfl_sync(0xffffffffu, r1, hb + e2 + 1);
            float rB2 = __shfl_sync(0xffffffffu, r2, hb + e2 + 1);
            float kvA[4] = {kA.x, kA.y, kA.z, kA.w};
            float kvB[4] = {kB.x, kB.y, kB.z, kB.w};
            float pa[4], pbv[4];
            #pragma unroll
            for (int i = 0; i < 4; i++) {
                float dlA = fmaf(rA0, pw0[i], fmaf(rA1, pw1[i], fmaf(rA2, pw2[i], pb[i])));
                float a0A = kvA[i] - qv[i] + dlA;
                pa[i] = fmaxf(fmaf(a0A, scA[i], shA[i]), 0.f);
                float dlB = fmaf(rB0, pw0[i], fmaf(rB1, pw1[i], fmaf(rB2, pw2[i], pb[i])));
                float a0B = kvB[i] - qv[i] + dlB;
                pbv[i] = fmaxf(fmaf(a0B, scA[i], shA[i]), 0.f);
            }
            float accA[8], accB[8];
            #pragma unroll
            for (int s = 0; s < 8; s++) {
                accA[s] = fmaf(pa[0], rW[s][0], fmaf(pa[1], rW[s][1],
                          fmaf(pa[2], rW[s][2], pa[3] * rW[s][3])));
                accB[s] = fmaf(pbv[0], rW[s][0], fmaf(pbv[1], rW[s][1],
                          fmaf(pbv[2], rW[s][2], pbv[3] * rW[s][3])));
            }
            #pragma unroll
            for (int s = 0; s < 8; s++) {
                accA[s] += __shfl_xor_sync(0xffffffffu, accA[s], 8);
                accB[s] += __shfl_xor_sync(0xffffffffu, accB[s], 8);
            }
            bool hb3 = (lane & 8) != 0;
            float c4A[4], c4B[4];
            #pragma unroll
            for (int i = 0; i < 4; i++) {
                c4A[i] = hb3 ? accA[4 + i] : accA[i];
                c4B[i] = hb3 ? accB[4 + i] : accB[i];
            }
            #pragma unroll
            for (int i = 0; i < 4; i++) {
                c4A[i] += __shfl_xor_sync(0xffffffffu, c4A[i], 4);
                c4B[i] += __shfl_xor_sync(0xffffffffu, c4B[i], 4);
            }
            bool hb2 = (lane & 4) != 0;
            float c2aA = hb2 ? c4A[2] : c4A[0];
            float c2bA = hb2 ? c4A[3] : c4A[1];
            float c2aB = hb2 ? c4B[2] : c4B[0];
            float c2bB = hb2 ? c4B[3] : c4B[1];
            c2aA += __shfl_xor_sync(0xffffffffu, c2aA, 2);
            c2bA += __shfl_xor_sync(0xffffffffu, c2bA, 2);
            c2aB += __shfl_xor_sync(0xffffffffu, c2aB, 2);
            c2bB += __shfl_xor_sync(0xffffffffu, c2bB, 2);
            bool hb1 = (lane & 2) != 0;
            float c1A = hb1 ? c2bA : c2aA;
            float c1B = hb1 ? c2bB : c2aB;
            c1A += __shfl_xor_sync(0xffffffffu, c1A, 1);
            c1B += __shfl_xor_sync(0xffffffffu, c1B, 1);
            if ((lane & 1) == 0) {
                float fA = c1A + w1bl;
                float fB = c1B + w1bl;
                g_a1[(ebase + e2) * 8 + s_mine] = fA;
                g_a1[(ebase + e2 + 1) * 8 + s_mine] = fB;
                ls += fA + fB;
                lq = fmaf(fA, fA, lq);
                lq = fmaf(fB, fB, lq);
            }
            kA = nkA; kB = nkB;
        }
    }
    if ((lane & 1) == 0) {
        atomicAdd(&ssum[s_mine], ls);
        atomicAdd(&ssq[s_mine], lq);
    }
    __syncthreads();
    if (tid < 8) {
        atomicAdd(&g_st[ST_W2 + tid], (double)ssum[tid]);
        atomicAdd(&g_st[ST_W2 + 8 + tid], (double)ssq[tid]);
    }
}

// ---------------- aggregate: grid-stride; a2 + softmax + weighted sum ----
__global__ void __launch_bounds__(256) k_aggr(const float* __restrict__ pbg,
                                              const float* __restrict__ pbb,
                                              const float* __restrict__ p2w,
                                              const float* __restrict__ p2b,
                                              const float* __restrict__ wb2g,
                                              const float* __restrict__ wb2b,
                                              const float* __restrict__ w2w,
                                              const float* __restrict__ w2b) {
    __shared__ float sAttn[8][2][16][8];
    __shared__ float sR[8][2][16][3];
    __shared__ int   sSrc[8][2][16];
    __shared__ float sRagg[8][2][8][3];
    __shared__ float sp2[64][4];
    __shared__ float sw2[64];
    __shared__ float sw2b[8];
    __shared__ float ssum[64], ssq[64];
    __shared__ float s_tsc[3], s_tsh[3], s_sc2[8], s_sh2[8];

    int tid = threadIdx.x;
    int warp = tid >> 5, lane = tid & 31;
    {
        int c = tid >> 2, j = tid & 3;
        sp2[c][j] = (j < 3) ? p2w[c * 3 + j] : p2b[c];
    }
    if (tid < 64) { sw2[tid] = w2w[tid]; ssum[tid] = 0.f; ssq[tid] = 0.f; }
    if (tid >= 64 && tid < 72) sw2b[tid - 64] = w2b[tid - 64];
    if (tid >= 72 && tid < 75)
        bn_coef(ST_T, 3, tid - 72, INV_E, pbg, pbb, s_tsc[tid - 72], s_tsh[tid - 72]);
    if (tid >= 80 && tid < 88)
        bn_coef(ST_W2, 8, tid - 80, INV_E, wb2g, wb2b, s_sc2[tid - 80], s_sh2[tid - 80]);
    __syncthreads();

    int sub = lane >> 4, el = lane & 15;
    int gl = lane & 7;
    int c0 = lane, c1 = lane + 32;

    // grid-stride over node groups of 16 (each warp owns 2 nodes per group)
    for (int grp = blockIdx.x; grp < NN / 16; grp += gridDim.x) {
        int nodeBase = grp * 16 + warp * 2;
        int node = nodeBase + sub;
        int e = node * 16 + el;
        int src = g_src[e];
        sSrc[warp][sub][el] = src;
        float4 t = g_t4[e];
        float r0 = fmaxf(fmaf(t.x, s_tsc[0], s_tsh[0]), 0.f);
        float r1 = fmaxf(fmaf(t.y, s_tsc[1], s_tsh[1]), 0.f);
        float r2 = fmaxf(fmaf(t.z, s_tsc[2], s_tsh[2]), 0.f);
        sR[warp][sub][el][0] = r0; sR[warp][sub][el][1] = r1; sR[warp][sub][el][2] = r2;

        float4 a1lo = *(float4*)&g_a1[e * 8];
        float4 a1hi = *(float4*)&g_a1[e * 8 + 4];
        float av[8] = {a1lo.x, a1lo.y, a1lo.z, a1lo.w, a1hi.x, a1hi.y, a1hi.z, a1hi.w};
        float pbn[8];
        #pragma unroll
        for (int s = 0; s < 8; s++)
            pbn[s] = fmaxf(fmaf(av[s], s_sc2[s], s_sh2[s]), 0.f);
        #pragma unroll
        for (int s = 0; s < 8; s++) {
            float a2 = sw2b[s];
            #pragma unroll
            for (int s2 = 0; s2 < 8; s2++) a2 = fmaf(pbn[s2], sw2[s * 8 + s2], a2);
            float mx = a2;
            #pragma unroll
            for (int m = 8; m; m >>= 1) mx = fmaxf(mx, __shfl_xor_sync(0xffffffffu, mx, m));
            float ex = __expf(a2 - mx);
            float sm = ex;
            #pragma unroll
            for (int m = 8; m; m >>= 1) sm += __shfl_xor_sync(0xffffffffu, sm, m);
            sAttn[warp][sub][el][s] = ex / sm;
        }
        __syncwarp();

        if (lane < 24) {
            int g = lane / 3, comp = lane % 3;
            #pragma unroll
            for (int sb = 0; sb < 2; sb++) {
                float rag = 0.f;
                #pragma unroll
                for (int e2 = 0; e2 < 16; e2++)
                    rag = fmaf(sAttn[warp][sb][e2][g], sR[warp][sb][e2][comp], rag);
                sRagg[warp][sb][g][comp] = rag;
            }
        }
        __syncwarp();

        #pragma unroll
        for (int sb = 0; sb < 2; sb++) {
            int nd = nodeBase + sb;
            float rag0 = sRagg[warp][sb][gl][0];
            float rag1 = sRagg[warp][sb][gl][1];
            float rag2 = sRagg[warp][sb][gl][2];
            float acc0 = fmaf(sp2[c0][0], rag0, fmaf(sp2[c0][1], rag1,
                         fmaf(sp2[c0][2], rag2, sp2[c0][3])));
            float acc1 = fmaf(sp2[c1][0], rag0, fmaf(sp2[c1][1], rag1,
                         fmaf(sp2[c1][2], rag2, sp2[c1][3])));
            #pragma unroll
            for (int e2 = 0; e2 < 16; e2++) {
                float at = sAttn[warp][sb][e2][gl];
                const float* vr = &g_v[sSrc[warp][sb][e2] * 64];
                acc0 = fmaf(at, vr[c0], acc0);
                acc1 = fmaf(at, vr[c1], acc1);
            }
            g_out[nd * 64 + c0] = acc0;
            g_out[nd * 64 + c1] = acc1;
            atomicAdd(&ssum[c0], acc0); atomicAdd(&ssq[c0], acc0 * acc0);
            atomicAdd(&ssum[c1], acc1); atomicAdd(&ssq[c1], acc1 * acc1);
        }
        __syncwarp();
    }
    __syncthreads();
    if (tid < 64) {
        atomicAdd(&g_st[ST_BN2 + tid], (double)ssum[tid]);
        atomicAdd(&g_st[ST_BN2 + 64 + tid], (double)ssq[tid]);
    }
}

// ---------------- GEMM 3: y3 = relu(bn2(out)) @ W3^T; bn3 stats ----------
__global__ void __launch_bounds__(256) k_lin3(const float* __restrict__ g2,
                                              const float* __restrict__ b2) {
    extern __shared__ float dyn[];
    float* sWT = dyn;
    float* sX  = dyn + 4096;
    __shared__ float ssc[64], ssh[64];
    __shared__ float ssum[64], ssq[64];
    int tid = threadIdx.x;
    #pragma unroll
    for (int i = tid; i < 4096; i += 256) sWT[i] = g_WT[4][i];
    if (tid < 64) {
        bn_coef(ST_BN2, 64, tid, INV_N, g2, b2, ssc[tid], ssh[tid]);
        ssum[tid] = 0.f; ssq[tid] = 0.f;
    }
    __syncthreads();
    int base = blockIdx.x * 128;
    #pragma unroll
    for (int i = tid; i < 8192; i += 256) {
        int n = i >> 6, c = i & 63;
        float y = g_out[(base + n) * 64 + c];
        sX[n * 68 + c] = fmaxf(fmaf(y, ssc[c], ssh[c]), 0.f);
    }
    __syncthreads();
    int o0 = (tid & 15) * 4;
    int n0 = (tid >> 4) * 8;
    float acc[8][4];
    #pragma unroll
    for (int i = 0; i < 8; i++)
        #pragma unroll
        for (int c = 0; c < 4; c++) acc[i][c] = 0.f;
    #pragma unroll
    for (int j = 0; j < 64; j += 4) {
        float4 xv[8];
        #pragma unroll
        for (int i = 0; i < 8; i++) xv[i] = *(float4*)(sX + (n0 + i) * 68 + j);
        #pragma unroll
        for (int jj = 0; jj < 4; jj++) {
            float4 wv = *(float4*)(sWT + (j + jj) * 64 + o0);
            #pragma unroll
            for (int i = 0; i < 8; i++) {
                float h = ((const float*)&xv[i])[jj];
                acc[i][0] = fmaf(h, wv.x, acc[i][0]);
                acc[i][1] = fmaf(h, wv.y, acc[i][1]);
                acc[i][2] = fmaf(h, wv.z, acc[i][2]);
                acc[i][3] = fmaf(h, wv.w, acc[i][3]);
            }
        }
    }
    float ts[4] = {0, 0, 0, 0}, tq[4] = {0, 0, 0, 0};
    #pragma unroll
    for (int i = 0; i < 8; i++) {
        *(float4*)&g_y3[(base + n0 + i) * 64 + o0] =
            make_float4(acc[i][0], acc[i][1], acc[i][2], acc[i][3]);
        #pragma unroll
        for (int c = 0; c < 4; c++) { ts[c] += acc[i][c]; tq[c] = fmaf(acc[i][c], acc[i][c], tq[c]); }
    }
    #pragma unroll
    for (int c = 0; c < 4; c++) {
        atomicAdd(&ssum[o0 + c], ts[c]);
        atomicAdd(&ssq[o0 + c], tq[c]);
    }
    __syncthreads();
    if (tid < 64) {
        atomicAdd(&g_st[ST_BN3 + tid], (double)ssum[tid]);
        atomicAdd(&g_st[ST_BN3 + 64 + tid], (double)ssq[tid]);
    }
}

// ---------------- final: relu(bn3(y3) + x) --------------------------------
__global__ void __launch_bounds__(256) k_final(const float* __restrict__ x,
                                               const float* __restrict__ g3,
                                               const float* __restrict__ b3,
                                               float* __restrict__ out) {
    __shared__ float ssc[64], ssh[64];
    int tid = threadIdx.x;
    if (tid < 64) bn_coef(ST_BN3, 64, tid, INV_N, g3, b3, ssc[tid], ssh[tid]);
    __syncthreads();
    int gid = blockIdx.x * 256 + tid;
    int i = gid * 4;
    int c0 = i & 63;
    float4 y = *(float4*)&g_y3[i];
    float4 xv = *(const float4*)&x[i];
    float4 r;
    r.x = fmaxf(fmaf(y.x, ssc[c0 + 0], ssh[c0 + 0]) + xv.x, 0.f);
    r.y = fmaxf(fmaf(y.y, ssc[c0 + 1], ssh[c0 + 1]) + xv.y, 0.f);
    r.z = fmaxf(fmaf(y.z, ssc[c0 + 2], ssh[c0 + 2]) + xv.z, 0.f);
    r.w = fmaxf(fmaf(y.w, ssc[c0 + 3], ssh[c0 + 3]) + xv.w, 0.f);
    *(float4*)&out[i] = r;
}

// ---------------- launch ---------------------------------------------------
extern "C" void kernel_launch(void* const* d_in, const int* in_sizes, int n_in,
                              void* d_out, int out_size) {
    const float* pos  = (const float*)d_in[0];
    const float* x    = (const float*)d_in[1];
    const float* W1   = (const float*)d_in[2];
    const float* Wk   = (const float*)d_in[3];
    const float* bk   = (const float*)d_in[4];
    const float* Wq   = (const float*)d_in[5];
    const float* bq   = (const float*)d_in[6];
    const float* Wv   = (const float*)d_in[7];
    const float* bv   = (const float*)d_in[8];
    const float* p1w  = (const float*)d_in[9];
    const float* p1b  = (const float*)d_in[10];
    const float* pbg  = (const float*)d_in[11];
    const float* pbb  = (const float*)d_in[12];
    const float* p2w  = (const float*)d_in[13];
    const float* p2b  = (const float*)d_in[14];
    const float* wb1g = (const float*)d_in[15];
    const float* wb1b = (const float*)d_in[16];
    const float* w1w  = (const float*)d_in[17];
    const float* w1b  = (const float*)d_in[18];
    const float* wb2g = (const float*)d_in[19];
    const float* wb2b = (const float*)d_in[20];
    const float* w2w  = (const float*)d_in[21];
    const float* w2b  = (const float*)d_in[22];
    const float* W3   = (const float*)d_in[23];
    const float* g1   = (const float*)d_in[24];
    const float* b1   = (const float*)d_in[25];
    const float* g2   = (const float*)d_in[26];
    const float* b2   = (const float*)d_in[27];
    const float* g3   = (const float*)d_in[28];
    const float* b3   = (const float*)d_in[29];
    const int*   ei   = (const int*)d_in[30];
    float* out = (float*)d_out;

    cudaFuncSetAttribute(k_early, cudaFuncAttributeMaxDynamicSharedMemorySize, GEMM_SMEM);
    cudaFuncSetAttribute(k_lin3,  cudaFuncAttributeMaxDynamicSharedMemorySize, GEMM_SMEM);
    cudaFuncSetAttribute(k_kq,    cudaFuncAttributeMaxDynamicSharedMemorySize, GEMM_SMEM);
    cudaFuncSetAttribute(k_a0v,   cudaFuncAttributeMaxDynamicSharedMemorySize, GEMM_SMEM);

    k_prep<<<80, 256>>>(W1, Wk, Wq, Wv, W3);
    k_early<<<256 + EE / 256, 256, GEMM_SMEM>>>(x, ei, pos, p1w, p1b);
    k_kq<<<NN / 128, 256, GEMM_SMEM>>>(bk, bq, g1, b1);
    k_a0v<<<256 + A0_EDGE_BLOCKS, 256, GEMM_SMEM>>>(bv, g1, b1, pbg, pbb, p2w, p2b);
    k_a1<<<A1_BLOCKS, 256>>>(pbg, pbb, p2w, p2b, wb1g, wb1b, w1w, w1b);
    k_aggr<<<AGGR_BLOCKS, 256>>>(pbg, pbb, p2w, p2b, wb2g, wb2b, w2w, w2b);
    k_lin3<<<NN / 128, 256, GEMM_SMEM>>>(g2, b2);
    k_final<<<(NN * CC) / 1024, 256>>>(x, g3, b3, out);
}

// round 17
// speedup vs baseline: 1.1976x; 1.0226x over previous
#include <cuda_runtime.h>

#define NN 32768
#define CC 64
#define KK 16
#define SS 8
#define EE (NN * KK)
#define EPS 1e-5f

// ---------------- scratch ----------------
__device__ float g_y1[NN * CC];
__device__ float g_k[NN * CC];
__device__ float g_q[NN * CC];
__device__ float g_v[NN * CC];
__device__ float g_a1[EE * SS];
__device__ float g_out[NN * CC];
__device__ float g_y3[NN * CC];
__device__ int   g_src[EE];
__device__ float4 g_t4[EE];
__device__ float g_WT[5][4096];   // [j*64+o]; 0=W1,1=Wk,2=Wq,3=Wv,4=W3

#define ST_BN1 0
#define ST_T   128
#define ST_W1  134
#define ST_W2  262
#define ST_BN2 278
#define ST_BN3 406
#define ST_TOT 534
__device__ double g_st[ST_TOT];

#define INV_N  (1.0 / (double)NN)
#define INV_E  (1.0 / (double)EE)

// dynamic smem: weights (4096) + X tile (128*68)
#define GEMM_SMEM ((4096 + 128 * 68) * 4)
#define EARLY_EDGE_BLOCKS 1072
#define A0_EDGE_BLOCKS 1072
#define A1_BLOCKS 888
#define AGGR_BLOCKS 592

__device__ __forceinline__ void bn_coef(int off, int nch, int c, double inv_cnt,
                                        const float* __restrict__ g,
                                        const float* __restrict__ b,
                                        float& scale, float& shift) {
    double m = g_st[off + c] * inv_cnt;
    double v = g_st[off + nch + c] * inv_cnt - m * m;
    float rs = rsqrtf(fmaxf((float)v, 0.f) + EPS);
    scale = rs * __ldg(&g[c]);
    shift = __ldg(&b[c]) - (float)m * scale;
}

// shared GEMM body: 128-node tile, 8 nodes x 4 outputs per thread
__device__ __forceinline__ void gemm_tile(const float* sWT, const float* sX,
                                          float* dstBase, int base, int tid,
                                          float bo0, float bo1, float bo2, float bo3) {
    int o0 = (tid & 15) * 4;
    int n0 = (tid >> 4) * 8;
    float acc[8][4];
    #pragma unroll
    for (int i = 0; i < 8; i++)
        #pragma unroll
        for (int c = 0; c < 4; c++) acc[i][c] = 0.f;
    #pragma unroll
    for (int j = 0; j < 64; j += 4) {
        float4 xv[8];
        #pragma unroll
        for (int i = 0; i < 8; i++) xv[i] = *(float4*)(sX + (n0 + i) * 68 + j);
        #pragma unroll
        for (int jj = 0; jj < 4; jj++) {
            float4 wv = *(float4*)(sWT + (j + jj) * 64 + o0);
            #pragma unroll
            for (int i = 0; i < 8; i++) {
                float h = ((const float*)&xv[i])[jj];
                acc[i][0] = fmaf(h, wv.x, acc[i][0]);
                acc[i][1] = fmaf(h, wv.y, acc[i][1]);
                acc[i][2] = fmaf(h, wv.z, acc[i][2]);
                acc[i][3] = fmaf(h, wv.w, acc[i][3]);
            }
        }
    }
    #pragma unroll
    for (int i = 0; i < 8; i++)
        *(float4*)&dstBase[(base + n0 + i) * 64 + o0] =
            make_float4(acc[i][0] + bo0, acc[i][1] + bo1, acc[i][2] + bo2, acc[i][3] + bo3);
}

// ---------------- prep: zero stats + transpose weights -------------------
__global__ void k_prep(const float* __restrict__ W1, const float* __restrict__ Wk,
                       const float* __restrict__ Wq, const float* __restrict__ Wv,
                       const float* __restrict__ W3) {
    int i = blockIdx.x * 256 + threadIdx.x;
    if (i < ST_TOT) g_st[i] = 0.0;
    if (i < 5 * 4096) {
        int m = i >> 12, r = i & 4095;
        int o = r >> 6, j = r & 63;
        const float* W = (m == 0) ? W1 : (m == 1) ? Wk : (m == 2) ? Wq : (m == 3) ? Wv : W3;
        g_WT[m][j * 64 + o] = W[o * 64 + j];
    }
}

// ---------------- early: lin1 (blocks 0..255) + cvt/t-stats (grid-stride)
__global__ void __launch_bounds__(256) k_early(const float* __restrict__ x,
                                               const int* __restrict__ ei32,
                                               const float* __restrict__ pos,
                                               const float* __restrict__ p1w,
                                               const float* __restrict__ p1b) {
    int tid = threadIdx.x;
    if (blockIdx.x < 256) {
        extern __shared__ float dyn[];
        float* sWT = dyn;
        float* sX  = dyn + 4096;
        __shared__ float ssum[64], ssq[64];
        #pragma unroll
        for (int i = tid; i < 4096; i += 256) sWT[i] = g_WT[0][i];
        if (tid < 64) { ssum[tid] = 0.f; ssq[tid] = 0.f; }
        int base = blockIdx.x * 128;
        #pragma unroll
        for (int i = tid; i < 8192; i += 256) {
            int n = i >> 6, c = i & 63;
            sX[n * 68 + c] = x[(base + n) * 64 + c];
        }
        __syncthreads();
        int o0 = (tid & 15) * 4;
        int n0 = (tid >> 4) * 8;
        float acc[8][4];
        #pragma unroll
        for (int i = 0; i < 8; i++)
            #pragma unroll
            for (int c = 0; c < 4; c++) acc[i][c] = 0.f;
        #pragma unroll
        for (int j = 0; j < 64; j += 4) {
            float4 xv[8];
            #pragma unroll
            for (int i = 0; i < 8; i++) xv[i] = *(float4*)(sX + (n0 + i) * 68 + j);
            #pragma unroll
            for (int jj = 0; jj < 4; jj++) {
                float4 wv = *(float4*)(sWT + (j + jj) * 64 + o0);
                #pragma unroll
                for (int i = 0; i < 8; i++) {
                    float h = ((const float*)&xv[i])[jj];
                    acc[i][0] = fmaf(h, wv.x, acc[i][0]);
                    acc[i][1] = fmaf(h, wv.y, acc[i][1]);
                    acc[i][2] = fmaf(h, wv.z, acc[i][2]);
                    acc[i][3] = fmaf(h, wv.w, acc[i][3]);
                }
            }
        }
        float ts[4] = {0, 0, 0, 0}, tq[4] = {0, 0, 0, 0};
        #pragma unroll
        for (int i = 0; i < 8; i++) {
            *(float4*)&g_y1[(base + n0 + i) * 64 + o0] =
                make_float4(acc[i][0], acc[i][1], acc[i][2], acc[i][3]);
            #pragma unroll
            for (int c = 0; c < 4; c++) { ts[c] += acc[i][c]; tq[c] = fmaf(acc[i][c], acc[i][c], tq[c]); }
        }
        #pragma unroll
        for (int c = 0; c < 4; c++) {
            atomicAdd(&ssum[o0 + c], ts[c]);
            atomicAdd(&ssq[o0 + c], tq[c]);
        }
        __syncthreads();
        if (tid < 64) {
            atomicAdd(&g_st[ST_BN1 + tid], (double)ssum[tid]);
            atomicAdd(&g_st[ST_BN1 + 64 + tid], (double)ssq[tid]);
        }
    } else {
        // ===== cvt: grid-stride over edges; stats accumulated in regs =====
        __shared__ float red[6];
        if (tid < 6) red[tid] = 0.f;
        bool is32 = (ei32[EE + 16] == 1) && (ei32[EE + 17] == 1) && (ei32[EE + 31] == 1);
        float w[9], b3[3];
        #pragma unroll
        for (int i = 0; i < 9; i++) w[i] = __ldg(&p1w[i]);
        #pragma unroll
        for (int i = 0; i < 3; i++) b3[i] = __ldg(&p1b[i]);
        __syncthreads();
        float s0 = 0, s1 = 0, s2 = 0, q0 = 0, q1 = 0, q2 = 0;
        int stride = (gridDim.x - 256) * 256;
        for (int e = (blockIdx.x - 256) * 256 + tid; e < EE; e += stride) {
            int src = is32 ? ei32[e] : ei32[2 * e];
            g_src[e] = src;
            int d = e >> 4;
            float rx = pos[src * 3 + 0] - pos[d * 3 + 0];
            float ry = pos[src * 3 + 1] - pos[d * 3 + 1];
            float rz = pos[src * 3 + 2] - pos[d * 3 + 2];
            float t0 = fmaf(w[0], rx, fmaf(w[1], ry, fmaf(w[2], rz, b3[0])));
            float t1 = fmaf(w[3], rx, fmaf(w[4], ry, fmaf(w[5], rz, b3[1])));
            float t2 = fmaf(w[6], rx, fmaf(w[7], ry, fmaf(w[8], rz, b3[2])));
            g_t4[e] = make_float4(t0, t1, t2, 0.f);
            s0 += t0; s1 += t1; s2 += t2;
            q0 = fmaf(t0, t0, q0); q1 = fmaf(t1, t1, q1); q2 = fmaf(t2, t2, q2);
        }
        #pragma unroll
        for (int m = 16; m; m >>= 1) {
            s0 += __shfl_xor_sync(0xffffffffu, s0, m);
            s1 += __shfl_xor_sync(0xffffffffu, s1, m);
            s2 += __shfl_xor_sync(0xffffffffu, s2, m);
            q0 += __shfl_xor_sync(0xffffffffu, q0, m);
            q1 += __shfl_xor_sync(0xffffffffu, q1, m);
            q2 += __shfl_xor_sync(0xffffffffu, q2, m);
        }
        if ((tid & 31) == 0) {
            atomicAdd(&red[0], s0); atomicAdd(&red[1], s1); atomicAdd(&red[2], s2);
            atomicAdd(&red[3], q0); atomicAdd(&red[4], q1); atomicAdd(&red[5], q2);
        }
        __syncthreads();
        if (tid < 6) atomicAdd(&g_st[ST_T + tid], (double)red[tid]);
    }
}

// ---------------- kq fused: one sX fill, weight reload between passes ----
__global__ void __launch_bounds__(256) k_kq(const float* __restrict__ bk,
                                            const float* __restrict__ bq,
                                            const float* __restrict__ g1,
                                            const float* __restrict__ b1) {
    extern __shared__ float dyn[];
    float* sWT = dyn;
    float* sX  = dyn + 4096;
    __shared__ float ssc[64], ssh[64];
    int tid = threadIdx.x;
    #pragma unroll
    for (int i = tid; i < 4096; i += 256) sWT[i] = g_WT[1][i];
    if (tid < 64) bn_coef(ST_BN1, 64, tid, INV_N, g1, b1, ssc[tid], ssh[tid]);
    __syncthreads();
    int base = blockIdx.x * 128;
    #pragma unroll
    for (int i = tid; i < 8192; i += 256) {
        int n = i >> 6, c = i & 63;
        float y = g_y1[(base + n) * 64 + c];
        sX[n * 68 + c] = fmaxf(fmaf(y, ssc[c], ssh[c]), 0.f);
    }
    __syncthreads();
    int o0 = (tid & 15) * 4;
    for (int m = 0; m < 2; m++) {
        const float* bias = (m == 0) ? bk : bq;
        float* dst = (m == 0) ? g_k : g_q;
        float bo0 = __ldg(&bias[o0]), bo1 = __ldg(&bias[o0 + 1]),
              bo2 = __ldg(&bias[o0 + 2]), bo3 = __ldg(&bias[o0 + 3]);
        gemm_tile(sWT, sX, dst, base, tid, bo0, bo1, bo2, bo3);
        if (m == 0) {
            __syncthreads();
            #pragma unroll
            for (int i = tid; i < 4096; i += 256) sWT[i] = g_WT[2][i];
            __syncthreads();
        }
    }
}

// ---------------- a0 stats (blocks 256+) co-scheduled with v GEMM (0..255)
__global__ void __launch_bounds__(256) k_a0v(const float* __restrict__ bv,
                                             const float* __restrict__ g1,
                                             const float* __restrict__ b1,
                                             const float* __restrict__ pbg,
                                             const float* __restrict__ pbb,
                                             const float* __restrict__ p2w,
                                             const float* __restrict__ p2b) {
    int tid = threadIdx.x;
    if (blockIdx.x < 256) {
        // ===== v = relu(bn1(y1)) @ Wv^T + bv =====
        extern __shared__ float dyn[];
        float* sWT = dyn;
        float* sX  = dyn + 4096;
        __shared__ float ssc[64], ssh[64];
        #pragma unroll
        for (int i = tid; i < 4096; i += 256) sWT[i] = g_WT[3][i];
        if (tid < 64) bn_coef(ST_BN1, 64, tid, INV_N, g1, b1, ssc[tid], ssh[tid]);
        __syncthreads();
        int base = blockIdx.x * 128;
        #pragma unroll
        for (int i = tid; i < 8192; i += 256) {
            int n = i >> 6, c = i & 63;
            float y = g_y1[(base + n) * 64 + c];
            sX[n * 68 + c] = fmaxf(fmaf(y, ssc[c], ssh[c]), 0.f);
        }
        __syncthreads();
        int o0 = (tid & 15) * 4;
        float bo0 = __ldg(&bv[o0]), bo1 = __ldg(&bv[o0 + 1]),
              bo2 = __ldg(&bv[o0 + 2]), bo3 = __ldg(&bv[o0 + 3]);
        gemm_tile(sWT, sX, g_v, base, tid, bo0, bo1, bo2, bo3);
        return;
    }
    // ===== a0 stats: node-blocked, 4-edge batch, late rr-shuffles =====
    __shared__ float ssum[64], ssq[64];
    __shared__ float s_tsc[3], s_tsh[3];
    if (tid < 64) { ssum[tid] = 0.f; ssq[tid] = 0.f; }
    if (tid >= 64 && tid < 67)
        bn_coef(ST_T, 3, tid - 64, INV_E, pbg, pbb, s_tsc[tid - 64], s_tsh[tid - 64]);
    int lane = tid & 31;
    int half = lane >> 4;
    int el = lane & 15;
    int c0 = el * 4;
    int hb = half << 4;
    float pw0[4], pw1[4], pw2[4], pb[4];
    #pragma unroll
    for (int i = 0; i < 4; i++) {
        pw0[i] = __ldg(&p2w[(c0 + i) * 3 + 0]);
        pw1[i] = __ldg(&p2w[(c0 + i) * 3 + 1]);
        pw2[i] = __ldg(&p2w[(c0 + i) * 3 + 2]);
        pb[i]  = __ldg(&p2b[c0 + i]);
    }
    float sums[4] = {0, 0, 0, 0}, sqs[4] = {0, 0, 0, 0};
    __syncthreads();
    float tsc[3], tsh[3];
    #pragma unroll
    for (int i = 0; i < 3; i++) { tsc[i] = s_tsc[i]; tsh[i] = s_tsh[i]; }
    int gw = ((blockIdx.x - 256) * 256 + tid) >> 5;
    int nw = ((gridDim.x - 256) * 256) >> 5;
    for (int np = gw; np < NN / 2; np += nw) {
        int node = 2 * np + half;
        int ebase = node * 16;
        int mySrc = g_src[ebase + el];
        float4 t = g_t4[ebase + el];
        float r0 = fmaxf(fmaf(t.x, tsc[0], tsh[0]), 0.f);
        float r1 = fmaxf(fmaf(t.y, tsc[1], tsh[1]), 0.f);
        float r2 = fmaxf(fmaf(t.z, tsc[2], tsh[2]), 0.f);
        float4 q4 = *(float4*)&g_q[node * 64 + c0];
        float qv[4] = {q4.x, q4.y, q4.z, q4.w};
        #pragma unroll
        for (int e2 = 0; e2 < 16; e2 += 4) {
            int s[4];
            #pragma unroll
            for (int j = 0; j < 4; j++)
                s[j] = __shfl_sync(0xffffffffu, mySrc, hb + e2 + j);
            float4 kk[4];
            #pragma unroll
            for (int j = 0; j < 4; j++) kk[j] = *(float4*)&g_k[s[j] * 64 + c0];
            #pragma unroll
            for (int j = 0; j < 4; j++) {
                float rr0 = __shfl_sync(0xffffffffu, r0, hb + e2 + j);
                float rr1 = __shfl_sync(0xffffffffu, r1, hb + e2 + j);
                float rr2 = __shfl_sync(0xffffffffu, r2, hb + e2 + j);
                float kv[4] = {kk[j].x, kk[j].y, kk[j].z, kk[j].w};
                #pragma unroll
                for (int i = 0; i < 4; i++) {
                    float dl = fmaf(rr0, pw0[i], fmaf(rr1, pw1[i],
                               fmaf(rr2, pw2[i], pb[i])));
                    float a0 = kv[i] - qv[i] + dl;
                    sums[i] += a0;
                    sqs[i] = fmaf(a0, a0, sqs[i]);
                }
            }
        }
    }
    #pragma unroll
    for (int i = 0; i < 4; i++) {
        atomicAdd(&ssum[c0 + i], sums[i]);
        atomicAdd(&ssq[c0 + i], sqs[i]);
    }
    __syncthreads();
    if (tid < 64) {
        atomicAdd(&g_st[ST_W1 + tid], (double)ssum[tid]);
        atomicAdd(&g_st[ST_W1 + 64 + tid], (double)ssq[tid]);
    }
}

// ---------------- a1: node-blocked; prefetched gathers, paired trees -----
__global__ void __launch_bounds__(256) k_a1(const float* __restrict__ pbg,
                                            const float* __restrict__ pbb,
                                            const float* __restrict__ p2w,
                                            const float* __restrict__ p2b,
                                            const float* __restrict__ wb1g,
                                            const float* __restrict__ wb1b,
                                            const float* __restrict__ w1w,
                                            const float* __restrict__ w1b) {
    __shared__ float ssum[8], ssq[8];
    __shared__ float s_tsc[3], s_tsh[3];
    __shared__ float s_scA[64], s_shA[64];
    int tid = threadIdx.x;
    if (tid < 8) { ssum[tid] = 0.f; ssq[tid] = 0.f; }
    if (tid >= 64 && tid < 67)
        bn_coef(ST_T, 3, tid - 64, INV_E, pbg, pbb, s_tsc[tid - 64], s_tsh[tid - 64]);
    if (tid < 64)
        bn_coef(ST_W1, 64, tid, INV_E, wb1g, wb1b, s_scA[tid], s_shA[tid]);
    int lane = tid & 31;
    int half = lane >> 4;
    int el = lane & 15;
    int c0 = el * 4;
    int hb = half << 4;
    float pw0[4], pw1[4], pw2[4], pb[4];
    #pragma unroll
    for (int i = 0; i < 4; i++) {
        pw0[i] = __ldg(&p2w[(c0 + i) * 3 + 0]);
        pw1[i] = __ldg(&p2w[(c0 + i) * 3 + 1]);
        pw2[i] = __ldg(&p2w[(c0 + i) * 3 + 2]);
        pb[i]  = __ldg(&p2b[c0 + i]);
    }
    float rW[8][4];
    #pragma unroll
    for (int s = 0; s < 8; s++)
        #pragma unroll
        for (int i = 0; i < 4; i++)
            rW[s][i] = __ldg(&w1w[s * 64 + c0 + i]);
    int s_mine = (lane >> 1) & 7;
    float w1bl = __ldg(&w1b[s_mine]);
    float ls = 0.f, lq = 0.f;
    __syncthreads();
    float tsc[3], tsh[3], scA[4], shA[4];
    #pragma unroll
    for (int i = 0; i < 3; i++) { tsc[i] = s_tsc[i]; tsh[i] = s_tsh[i]; }
    #pragma unroll
    for (int i = 0; i < 4; i++) { scA[i] = s_scA[c0 + i]; shA[i] = s_shA[c0 + i]; }
    int gw = (blockIdx.x * 256 + tid) >> 5;
    int nw = (gridDim.x * 256) >> 5;
    for (int np = gw; np < NN / 2; np += nw) {
        int node = 2 * np + half;
        int ebase = node * 16;
        int mySrc = g_src[ebase + el];
        float4 t = g_t4[ebase + el];
        float r0 = fmaxf(fmaf(t.x, tsc[0], tsh[0]), 0.f);
        float r1 = fmaxf(fmaf(t.y, tsc[1], tsh[1]), 0.f);
        float r2 = fmaxf(fmaf(t.z, tsc[2], tsh[2]), 0.f);
        float4 q4 = *(float4*)&g_q[node * 64 + c0];
        float qv[4] = {q4.x, q4.y, q4.z, q4.w};
        // prefetch first pair
        int srcA = __shfl_sync(0xffffffffu, mySrc, hb + 0);
        int srcB = __shfl_sync(0xffffffffu, mySrc, hb + 1);
        float4 kA = *(float4*)&g_k[srcA * 64 + c0];
        float4 kB = *(float4*)&g_k[srcB * 64 + c0];
        #pragma unroll
        for (int e2 = 0; e2 < 16; e2 += 2) {
            float4 nkA, nkB;
            if (e2 < 14) {
                int nsA = __shfl_sync(0xffffffffu, mySrc, hb + e2 + 2);
                int nsB = __shfl_sync(0xffffffffu, mySrc, hb + e2 + 3);
                nkA = *(float4*)&g_k[nsA * 64 + c0];
                nkB = *(float4*)&g_k[nsB * 64 + c0];
            }
            float rA0 = __shfl_sync(0xffffffffu, r0, hb + e2);
            float rA1 = __shfl_sync(0xffffffffu, r1, hb + e2);
            float rA2 = __shfl_sync(0xffffffffu, r2, hb + e2);
            float rB0 = __shfl_sync(0xffffffffu, r0, hb + e2 + 1);
            float rB1 = __shfl_sync(0xffffffffu, r1, hb + e2 + 1);
            float rB2 = __shfl_sync(0xffffffffu, r2, hb + e2 + 1);
            float kvA[4] = {kA.x, kA.y, kA.z, kA.w};
            float kvB[4] = {kB.x, kB.y, kB.z, kB.w};
            float pa[4], pbv[4];
            #pragma unroll
            for (int i = 0; i < 4; i++) {
                float dlA = fmaf(rA0, pw0[i], fmaf(rA1, pw1[i], fmaf(rA2, pw2[i], pb[i])));
                float a0A = kvA[i] - qv[i] + dlA;
                pa[i] = fmaxf(fmaf(a0A, scA[i], shA[i]), 0.f);
                float dlB = fmaf(rB0, pw0[i], fmaf(rB1, pw1[i], fmaf(rB2, pw2[i], pb[i])));
                float a0B = kvB[i] - qv[i] + dlB;
                pbv[i] = fmaxf(fmaf(a0B, scA[i], shA[i]), 0.f);
            }
            float accA[8], accB[8];
            #pragma unroll
            for (int s = 0; s < 8; s++) {
                accA[s] = fmaf(pa[0], rW[s][0], fmaf(pa[1], rW[s][1],
                          fmaf(pa[2], rW[s][2], pa[3] * rW[s][3])));
                accB[s] = fmaf(pbv[0], rW[s][0], fmaf(pbv[1], rW[s][1],
                          fmaf(pbv[2], rW[s][2], pbv[3] * rW[s][3])));
            }
            #pragma unroll
            for (int s = 0; s < 8; s++) {
                accA[s] += __shfl_xor_sync(0xffffffffu, accA[s], 8);
                accB[s] += __shfl_xor_sync(0xffffffffu, accB[s], 8);
            }
            bool hb3 = (lane & 8) != 0;
            float c4A[4], c4B[4];
            #pragma unroll
            for (int i = 0; i < 4; i++) {
                c4A[i] = hb3 ? accA[4 + i] : accA[i];
                c4B[i] = hb3 ? accB[4 + i] : accB[i];
            }
            #pragma unroll
            for (int i = 0; i < 4; i++) {
                c4A[i] += __shfl_xor_sync(0xffffffffu, c4A[i], 4);
                c4B[i] += __shfl_xor_sync(0xffffffffu, c4B[i], 4);
            }
            bool hb2 = (lane & 4) != 0;
            float c2aA = hb2 ? c4A[2] : c4A[0];
            float c2bA = hb2 ? c4A[3] : c4A[1];
            float c2aB = hb2 ? c4B[2] : c4B[0];
            float c2bB = hb2 ? c4B[3] : c4B[1];
            c2aA += __shfl_xor_sync(0xffffffffu, c2aA, 2);
            c2bA += __shfl_xor_sync(0xffffffffu, c2bA, 2);
            c2aB += __shfl_xor_sync(0xffffffffu, c2aB, 2);
            c2bB += __shfl_xor_sync(0xffffffffu, c2bB, 2);
            bool hb1 = (lane & 2) != 0;
            float c1A = hb1 ? c2bA : c2aA;
            float c1B = hb1 ? c2bB : c2aB;
            c1A += __shfl_xor_sync(0xffffffffu, c1A, 1);
            c1B += __shfl_xor_sync(0xffffffffu, c1B, 1);
            if ((lane & 1) == 0) {
                float fA = c1A + w1bl;
                float fB = c1B + w1bl;
                g_a1[(ebase + e2) * 8 + s_mine] = fA;
                g_a1[(ebase + e2 + 1) * 8 + s_mine] = fB;
                ls += fA + fB;
                lq = fmaf(fA, fA, lq);
                lq = fmaf(fB, fB, lq);
            }
            kA = nkA; kB = nkB;
        }
    }
    if ((lane & 1) == 0) {
        atomicAdd(&ssum[s_mine], ls);
        atomicAdd(&ssq[s_mine], lq);
    }
    __syncthreads();
    if (tid < 8) {
        atomicAdd(&g_st[ST_W2 + tid], (double)ssum[tid]);
        atomicAdd(&g_st[ST_W2 + 8 + tid], (double)ssq[tid]);
    }
}

// ---------------- aggregate: grid-stride; a2 + softmax + weighted sum ----
__global__ void __launch_bounds__(256) k_aggr(const float* __restrict__ pbg,
                                              const float* __restrict__ pbb,
                                              const float* __restrict__ p2w,
                                              const float* __restrict__ p2b,
                                              const float* __restrict__ wb2g,
                                              const float* __restrict__ wb2b,
                                              const float* __restrict__ w2w,
                                              const float* __restrict__ w2b) {
    __shared__ float sAttn[8][2][16][8];
    __shared__ float sR[8][2][16][3];
    __shared__ int   sSrc[8][2][16];
    __shared__ float sRagg[8][2][8][3];
    __shared__ float sp2[64][4];
    __shared__ float sw2[64];
    __shared__ float sw2b[8];
    __shared__ float ssum[64], ssq[64];
    __shared__ float s_tsc[3], s_tsh[3], s_sc2[8], s_sh2[8];

    int tid = threadIdx.x;
    int warp = tid >> 5, lane = tid & 31;
    {
        int c = tid >> 2, j = tid & 3;
        sp2[c][j] = (j < 3) ? p2w[c * 3 + j] : p2b[c];
    }
    if (tid < 64) { sw2[tid] = w2w[tid]; ssum[tid] = 0.f; ssq[tid] = 0.f; }
    if (tid >= 64 && tid < 72) sw2b[tid - 64] = w2b[tid - 64];
    if (tid >= 72 && tid < 75)
        bn_coef(ST_T, 3, tid - 72, INV_E, pbg, pbb, s_tsc[tid - 72], s_tsh[tid - 72]);
    if (tid >= 80 && tid < 88)
        bn_coef(ST_W2, 8, tid - 80, INV_E, wb2g, wb2b, s_sc2[tid - 80], s_sh2[tid - 80]);
    __syncthreads();

    int sub = lane >> 4, el = lane & 15;
    int gl = lane & 7;
    int c0 = lane, c1 = lane + 32;

    for (int grp = blockIdx.x; grp < NN / 16; grp += gridDim.x) {
        int nodeBase = grp * 16 + warp * 2;
        int node = nodeBase + sub;
        int e = node * 16 + el;
        int src = g_src[e];
        sSrc[warp][sub][el] = src;
        float4 t = g_t4[e];
        float r0 = fmaxf(fmaf(t.x, s_tsc[0], s_tsh[0]), 0.f);
        float r1 = fmaxf(fmaf(t.y, s_tsc[1], s_tsh[1]), 0.f);
        float r2 = fmaxf(fmaf(t.z, s_tsc[2], s_tsh[2]), 0.f);
        sR[warp][sub][el][0] = r0; sR[warp][sub][el][1] = r1; sR[warp][sub][el][2] = r2;

        float4 a1lo = *(float4*)&g_a1[e * 8];
        float4 a1hi = *(float4*)&g_a1[e * 8 + 4];
        float av[8] = {a1lo.x, a1lo.y, a1lo.z, a1lo.w, a1hi.x, a1hi.y, a1hi.z, a1hi.w};
        float pbn[8];
        #pragma unroll
        for (int s = 0; s < 8; s++)
            pbn[s] = fmaxf(fmaf(av[s], s_sc2[s], s_sh2[s]), 0.f);
        #pragma unroll
        for (int s = 0; s < 8; s++) {
            float a2 = sw2b[s];
            #pragma unroll
            for (int s2 = 0; s2 < 8; s2++) a2 = fmaf(pbn[s2], sw2[s * 8 + s2], a2);
            float mx = a2;
            #pragma unroll
            for (int m = 8; m; m >>= 1) mx = fmaxf(mx, __shfl_xor_sync(0xffffffffu, mx, m));
            float ex = __expf(a2 - mx);
            float sm = ex;
            #pragma unroll
            for (int m = 8; m; m >>= 1) sm += __shfl_xor_sync(0xffffffffu, sm, m);
            sAttn[warp][sub][el][s] = ex / sm;
        }
        __syncwarp();

        if (lane < 24) {
            int g = lane / 3, comp = lane % 3;
            #pragma unroll
            for (int sb = 0; sb < 2; sb++) {
                float rag = 0.f;
                #pragma unroll
                for (int e2 = 0; e2 < 16; e2++)
                    rag = fmaf(sAttn[warp][sb][e2][g], sR[warp][sb][e2][comp], rag);
                sRagg[warp][sb][g][comp] = rag;
            }
        }
        __syncwarp();

        #pragma unroll
        for (int sb = 0; sb < 2; sb++) {
            int nd = nodeBase + sb;
            float rag0 = sRagg[warp][sb][gl][0];
            float rag1 = sRagg[warp][sb][gl][1];
            float rag2 = sRagg[warp][sb][gl][2];
            float acc0 = fmaf(sp2[c0][0], rag0, fmaf(sp2[c0][1], rag1,
                         fmaf(sp2[c0][2], rag2, sp2[c0][3])));
            float acc1 = fmaf(sp2[c1][0], rag0, fmaf(sp2[c1][1], rag1,
                         fmaf(sp2[c1][2], rag2, sp2[c1][3])));
            #pragma unroll
            for (int e2 = 0; e2 < 16; e2++) {
                float at = sAttn[warp][sb][e2][gl];
                const float* vr = &g_v[sSrc[warp][sb][e2] * 64];
                acc0 = fmaf(at, vr[c0], acc0);
                acc1 = fmaf(at, vr[c1], acc1);
            }
            g_out[nd * 64 + c0] = acc0;
            g_out[nd * 64 + c1] = acc1;
            atomicAdd(&ssum[c0], acc0); atomicAdd(&ssq[c0], acc0 * acc0);
            atomicAdd(&ssum[c1], acc1); atomicAdd(&ssq[c1], acc1 * acc1);
        }
        __syncwarp();
    }
    __syncthreads();
    if (tid < 64) {
        atomicAdd(&g_st[ST_BN2 + tid], (double)ssum[tid]);
        atomicAdd(&g_st[ST_BN2 + 64 + tid], (double)ssq[tid]);
    }
}

// ---------------- GEMM 3: y3 = relu(bn2(out)) @ W3^T; bn3 stats ----------
__global__ void __launch_bounds__(256) k_lin3(const float* __restrict__ g2,
                                              const float* __restrict__ b2) {
    extern __shared__ float dyn[];
    float* sWT = dyn;
    float* sX  = dyn + 4096;
    __shared__ float ssc[64], ssh[64];
    __shared__ float ssum[64], ssq[64];
    int tid = threadIdx.x;
    #pragma unroll
    for (int i = tid; i < 4096; i += 256) sWT[i] = g_WT[4][i];
    if (tid < 64) {
        bn_coef(ST_BN2, 64, tid, INV_N, g2, b2, ssc[tid], ssh[tid]);
        ssum[tid] = 0.f; ssq[tid] = 0.f;
    }
    __syncthreads();
    int base = blockIdx.x * 128;
    #pragma unroll
    for (int i = tid; i < 8192; i += 256) {
        int n = i >> 6, c = i & 63;
        float y = g_out[(base + n) * 64 + c];
        sX[n * 68 + c] = fmaxf(fmaf(y, ssc[c], ssh[c]), 0.f);
    }
    __syncthreads();
    int o0 = (tid & 15) * 4;
    int n0 = (tid >> 4) * 8;
    float acc[8][4];
    #pragma unroll
    for (int i = 0; i < 8; i++)
        #pragma unroll
        for (int c = 0; c < 4; c++) acc[i][c] = 0.f;
    #pragma unroll
    for (int j = 0; j < 64; j += 4) {
        float4 xv[8];
        #pragma unroll
        for (int i = 0; i < 8; i++) xv[i] = *(float4*)(sX + (n0 + i) * 68 + j);
        #pragma unroll
        for (int jj = 0; jj < 4; jj++) {
            float4 wv = *(float4*)(sWT + (j + jj) * 64 + o0);
            #pragma unroll
            for (int i = 0; i < 8; i++) {
                float h = ((const float*)&xv[i])[jj];
                acc[i][0] = fmaf(h, wv.x, acc[i][0]);
                acc[i][1] = fmaf(h, wv.y, acc[i][1]);
                acc[i][2] = fmaf(h, wv.z, acc[i][2]);
                acc[i][3] = fmaf(h, wv.w, acc[i][3]);
            }
        }
    }
    float ts[4] = {0, 0, 0, 0}, tq[4] = {0, 0, 0, 0};
    #pragma unroll
    for (int i = 0; i < 8; i++) {
        *(float4*)&g_y3[(base + n0 + i) * 64 + o0] =
            make_float4(acc[i][0], acc[i][1], acc[i][2], acc[i][3]);
        #pragma unroll
        for (int c = 0; c < 4; c++) { ts[c] += acc[i][c]; tq[c] = fmaf(acc[i][c], acc[i][c], tq[c]); }
    }
    #pragma unroll
    for (int c = 0; c < 4; c++) {
        atomicAdd(&ssum[o0 + c], ts[c]);
        atomicAdd(&ssq[o0 + c], tq[c]);
    }
    __syncthreads();
    if (tid < 64) {
        atomicAdd(&g_st[ST_BN3 + tid], (double)ssum[tid]);
        atomicAdd(&g_st[ST_BN3 + 64 + tid], (double)ssq[tid]);
    }
}

// ---------------- final: relu(bn3(y3) + x) --------------------------------
__global__ void __launch_bounds__(256) k_final(const float* __restrict__ x,
                                               const float* __restrict__ g3,
                                               const float* __restrict__ b3,
                                               float* __restrict__ out) {
    __shared__ float ssc[64], ssh[64];
    int tid = threadIdx.x;
    if (tid < 64) bn_coef(ST_BN3, 64, tid, INV_N, g3, b3, ssc[tid], ssh[tid]);
    __syncthreads();
    int gid = blockIdx.x * 256 + tid;
    int i = gid * 4;
    int c0 = i & 63;
    float4 y = *(float4*)&g_y3[i];
    float4 xv = *(const float4*)&x[i];
    float4 r;
    r.x = fmaxf(fmaf(y.x, ssc[c0 + 0], ssh[c0 + 0]) + xv.x, 0.f);
    r.y = fmaxf(fmaf(y.y, ssc[c0 + 1], ssh[c0 + 1]) + xv.y, 0.f);
    r.z = fmaxf(fmaf(y.z, ssc[c0 + 2], ssh[c0 + 2]) + xv.z, 0.f);
    r.w = fmaxf(fmaf(y.w, ssc[c0 + 3], ssh[c0 + 3]) + xv.w, 0.f);
    *(float4*)&out[i] = r;
}

// ---------------- launch ---------------------------------------------------
extern "C" void kernel_launch(void* const* d_in, const int* in_sizes, int n_in,
                              void* d_out, int out_size) {
    const float* pos  = (const float*)d_in[0];
    const float* x    = (const float*)d_in[1];
    const float* W1   = (const float*)d_in[2];
    const float* Wk   = (const float*)d_in[3];
    const float* bk   = (const float*)d_in[4];
    const float* Wq   = (const float*)d_in[5];
    const float* bq   = (const float*)d_in[6];
    const float* Wv   = (const float*)d_in[7];
    const float* bv   = (const float*)d_in[8];
    const float* p1w  = (const float*)d_in[9];
    const float* p1b  = (const float*)d_in[10];
    const float* pbg  = (const float*)d_in[11];
    const float* pbb  = (const float*)d_in[12];
    const float* p2w  = (const float*)d_in[13];
    const float* p2b  = (const float*)d_in[14];
    const float* wb1g = (const float*)d_in[15];
    const float* wb1b = (const float*)d_in[16];
    const float* w1w  = (const float*)d_in[17];
    const float* w1b  = (const float*)d_in[18];
    const float* wb2g = (const float*)d_in[19];
    const float* wb2b = (const float*)d_in[20];
    const float* w2w  = (const float*)d_in[21];
    const float* w2b  = (const float*)d_in[22];
    const float* W3   = (const float*)d_in[23];
    const float* g1   = (const float*)d_in[24];
    const float* b1   = (const float*)d_in[25];
    const float* g2   = (const float*)d_in[26];
    const float* b2   = (const float*)d_in[27];
    const float* g3   = (const float*)d_in[28];
    const float* b3   = (const float*)d_in[29];
    const int*   ei   = (const int*)d_in[30];
    float* out = (float*)d_out;

    cudaFuncSetAttribute(k_early, cudaFuncAttributeMaxDynamicSharedMemorySize, GEMM_SMEM);
    cudaFuncSetAttribute(k_lin3,  cudaFuncAttributeMaxDynamicSharedMemorySize, GEMM_SMEM);
    cudaFuncSetAttribute(k_kq,    cudaFuncAttributeMaxDynamicSharedMemorySize, GEMM_SMEM);
    cudaFuncSetAttribute(k_a0v,   cudaFuncAttributeMaxDynamicSharedMemorySize, GEMM_SMEM);

    k_prep<<<80, 256>>>(W1, Wk, Wq, Wv, W3);
    k_early<<<256 + EARLY_EDGE_BLOCKS, 256, GEMM_SMEM>>>(x, ei, pos, p1w, p1b);
    k_kq<<<NN / 128, 256, GEMM_SMEM>>>(bk, bq, g1, b1);
    k_a0v<<<256 + A0_EDGE_BLOCKS, 256, GEMM_SMEM>>>(bv, g1, b1, pbg, pbb, p2w, p2b);
    k_a1<<<A1_BLOCKS, 256>>>(pbg, pbb, p2w, p2b, wb1g, wb1b, w1w, w1b);
    k_aggr<<<AGGR_BLOCKS, 256>>>(pbg, pbb, p2w, p2b, wb2g, wb2b, w2w, w2b);
    k_lin3<<<NN / 128, 256, GEMM_SMEM>>>(g2, b2);
    k_final<<<(NN * CC) / 1024, 256>>>(x, g3, b3, out);
}